// round 10
// baseline (speedup 1.0000x reference)
#include <cuda_runtime.h>
#include <cuda_bf16.h>
#include <cstdint>

// ---------------------------------------------------------------------------
// Problem constants
// ---------------------------------------------------------------------------
#define BATCH 4
#define DMODEL 768
#define NHEAD 12
#define HDIM 64
#define NLVL 3
#define NPT 4
#define LQ 4096           // 64 x 64 query grid
#define LIN 16464         // 112*112 + 56*56 + 28*28
#define NOFF 288          // NH*NL*NP*2
#define NATT 144          // NH*NL*NP
#define NCOMB 432         // NOFF+NATT
#define NCOMB_PAD 512

// GEMM tiling
#define BM 128
#define BN 128
#define BK 64
#define ROWE 72            // bf16 elements per SMEM row (64 + 8 pad) = 144 B
#define KTILES (DMODEL / BK)   // 12
#define TILEB (BM * ROWE * 2)  // 18432 B per matrix-stage
#define NSTAGE 4
#define GEMM_SMEM (NSTAGE * 2 * TILEB)  // 147456 B

// ---------------------------------------------------------------------------
// Scratch (device globals; no runtime allocation allowed)
// ---------------------------------------------------------------------------
__device__ __nv_bfloat16 g_qln[(size_t)BATCH * LQ * DMODEL];
__device__ __nv_bfloat16 g_fln[(size_t)BATCH * LIN * DMODEL];
__device__ __nv_bfloat16 g_val[(size_t)BATCH * LIN * DMODEL];
__device__ float         g_off[(size_t)BATCH * LQ * NOFF];
__device__ float         g_aw [(size_t)BATCH * LQ * NATT];
__device__ __nv_bfloat16 g_sam[(size_t)BATCH * LQ * DMODEL];
__device__ __nv_bfloat16 g_WvalT[DMODEL * DMODEL];        // [n][k]
__device__ __nv_bfloat16 g_WoutT[DMODEL * DMODEL];        // [n][k]
__device__ __nv_bfloat16 g_WcombT[NCOMB_PAD * DMODEL];    // [n][k], rows >=432 zero

// ---------------------------------------------------------------------------
// helpers
// ---------------------------------------------------------------------------
__device__ __forceinline__ uint32_t smem_u32(const void* p) {
    uint32_t a;
    asm("{ .reg .u64 t; cvta.to.shared.u64 t, %1; cvt.u32.u64 %0, t; }" : "=r"(a) : "l"(p));
    return a;
}

#define CP_ASYNC16(sp, gp) \
    asm volatile("cp.async.cg.shared.global [%0], [%1], 16;" :: "r"(sp), "l"(gp) : "memory")
#define CP_COMMIT() asm volatile("cp.async.commit_group;" ::: "memory")
#define CP_WAIT2()  asm volatile("cp.async.wait_group 2;" ::: "memory")

#define LDSM_X4(r, addr)                                                      \
    asm volatile("ldmatrix.sync.aligned.m8n8.x4.shared.b16 {%0,%1,%2,%3}, [%4];" \
        : "=r"((r)[0]), "=r"((r)[1]), "=r"((r)[2]), "=r"((r)[3]) : "r"(addr))
#define LDSM_X2(r, addr)                                                      \
    asm volatile("ldmatrix.sync.aligned.m8n8.x2.shared.b16 {%0,%1}, [%2];"    \
        : "=r"((r)[0]), "=r"((r)[1]) : "r"(addr))

#define MMA_16816(c, a, b)                                                    \
    asm volatile("mma.sync.aligned.m16n8k16.row.col.f32.bf16.bf16.f32 "       \
        "{%0,%1,%2,%3}, {%4,%5,%6,%7}, {%8,%9}, {%0,%1,%2,%3};"               \
        : "+f"((c)[0]), "+f"((c)[1]), "+f"((c)[2]), "+f"((c)[3])              \
        : "r"((a)[0]), "r"((a)[1]), "r"((a)[2]), "r"((a)[3]),                 \
          "r"((b)[0]), "r"((b)[1]))

// ---------------------------------------------------------------------------
// Tiled transpose fp32 [K,N] -> bf16 [N,K]  (32x32 smem tiles, coalesced)
// ---------------------------------------------------------------------------
__global__ void __launch_bounds__(256) wtransT_kernel(
    const float* __restrict__ W, __nv_bfloat16* __restrict__ Wt, int K, int N)
{
    __shared__ float t[32][33];
    const int kb = blockIdx.x * 32, nb = blockIdx.y * 32;
    const int tx = threadIdx.x & 31, ty = threadIdx.x >> 5;
#pragma unroll
    for (int i = 0; i < 32; i += 8) {
        int k = kb + ty + i, n = nb + tx;
        t[ty + i][tx] = (k < K && n < N) ? W[(size_t)k * N + n] : 0.f;
    }
    __syncthreads();
#pragma unroll
    for (int i = 0; i < 32; i += 8) {
        int n = nb + ty + i, k = kb + tx;
        if (n < N && k < K)
            Wt[(size_t)n * K + k] = __float2bfloat16(t[tx][ty + i]);
    }
}

// combined off+attn transpose into padded [NCOMB_PAD, K]; rows >= NCOMB get 0
__global__ void __launch_bounds__(256) wtransC_kernel(
    const float* __restrict__ Woff, const float* __restrict__ Wattn,
    __nv_bfloat16* __restrict__ Wt)
{
    __shared__ float t[32][33];
    const int kb = blockIdx.x * 32, nb = blockIdx.y * 32;
    const int tx = threadIdx.x & 31, ty = threadIdx.x >> 5;
#pragma unroll
    for (int i = 0; i < 32; i += 8) {
        int k = kb + ty + i, n = nb + tx;
        float v = 0.f;
        if (k < DMODEL) {
            if (n < NOFF) v = Woff[(size_t)k * NOFF + n];
            else if (n < NCOMB) v = Wattn[(size_t)k * NATT + (n - NOFF)];
        }
        t[ty + i][tx] = v;
    }
    __syncthreads();
#pragma unroll
    for (int i = 0; i < 32; i += 8) {
        int n = nb + ty + i, k = kb + tx;
        if (n < NCOMB_PAD && k < DMODEL)
            Wt[(size_t)n * DMODEL + k] = __float2bfloat16(t[tx][ty + i]);
    }
}

// ---------------------------------------------------------------------------
// LayerNorm: one warp per row (768), float4 loads, shuffle-only reduction
// ---------------------------------------------------------------------------
__global__ void __launch_bounds__(256) ln_kernel(
    const float* __restrict__ x, const float* __restrict__ g,
    const float* __restrict__ b, __nv_bfloat16* __restrict__ out, int nrows)
{
    const int row = blockIdx.x * 8 + (threadIdx.x >> 5);
    const int lane = threadIdx.x & 31;
    if (row >= nrows) return;
    const float4* xr = reinterpret_cast<const float4*>(x + (size_t)row * DMODEL);
    float4 v[6];
    float s = 0.f, s2 = 0.f;
#pragma unroll
    for (int i = 0; i < 6; i++) {
        v[i] = xr[i * 32 + lane];
        s  += v[i].x + v[i].y + v[i].z + v[i].w;
        s2 += v[i].x * v[i].x + v[i].y * v[i].y + v[i].z * v[i].z + v[i].w * v[i].w;
    }
#pragma unroll
    for (int o = 16; o > 0; o >>= 1) {
        s  += __shfl_xor_sync(0xFFFFFFFFu, s,  o);
        s2 += __shfl_xor_sync(0xFFFFFFFFu, s2, o);
    }
    const float mean = s * (1.f / DMODEL);
    const float var  = s2 * (1.f / DMODEL) - mean * mean;
    const float rstd = rsqrtf(var + 1e-6f);
    const float4* gp = reinterpret_cast<const float4*>(g);
    const float4* bp = reinterpret_cast<const float4*>(b);
    uint2* o = reinterpret_cast<uint2*>(out + (size_t)row * DMODEL);
#pragma unroll
    for (int i = 0; i < 6; i++) {
        float4 gv = gp[i * 32 + lane];
        float4 bv = bp[i * 32 + lane];
        __nv_bfloat162 p0, p1;
        p0.x = __float2bfloat16((v[i].x - mean) * rstd * gv.x + bv.x);
        p0.y = __float2bfloat16((v[i].y - mean) * rstd * gv.y + bv.y);
        p1.x = __float2bfloat16((v[i].z - mean) * rstd * gv.z + bv.z);
        p1.y = __float2bfloat16((v[i].w - mean) * rstd * gv.w + bv.w);
        uint2 w;
        w.x = *reinterpret_cast<uint32_t*>(&p0);
        w.y = *reinterpret_cast<uint32_t*>(&p1);
        o[i * 32 + lane] = w;
    }
}

// ---------------------------------------------------------------------------
// mma.sync bf16 GEMM: C[M, gridDim.y*128] = A[M,768] @ Bt[N,768]^T (+bias)
//   CTA 128x128, 8 warps (2x4), warp tile 64x32, 4-stage cp.async pipeline,
//   ONE __syncthreads per k-tile.
// EPI 0: bf16 C        EPI 1: split off(288)/attn(144) float
// EPI 2: float out = resid + gamma*(acc+bias)
// ---------------------------------------------------------------------------
template <int EPI>
__global__ void __launch_bounds__(256) gemm_mma_kernel(
    const __nv_bfloat16* __restrict__ A, const __nv_bfloat16* __restrict__ Bt,
    int M, const float* __restrict__ bias0, const float* __restrict__ bias1,
    void* __restrict__ out0, void* __restrict__ out1,
    const float* __restrict__ resid, const float* __restrict__ gamma)
{
    extern __shared__ char smem[];
    const uint32_t sbase = smem_u32(smem);

    const int tid  = threadIdx.x;
    const int wid  = tid >> 5;
    const int lane = tid & 31;
    const int wm   = wid >> 2;        // 0..1
    const int wn   = wid & 3;         // 0..3
    const int m0   = blockIdx.x * BM;
    const int n0   = blockIdx.y * BN;

    float acc[4][4][4];
#pragma unroll
    for (int mi = 0; mi < 4; mi++)
#pragma unroll
        for (int ni = 0; ni < 4; ni++)
#pragma unroll
            for (int r = 0; r < 4; r++) acc[mi][ni][r] = 0.f;

    // stage st: A at sbase + st*2*TILEB, B at +TILEB
    auto load_tile = [&](int kt, int st) {
        const int k0 = kt * BK;
        const uint32_t aO = sbase + st * 2 * TILEB;
        const uint32_t bO = aO + TILEB;
#pragma unroll
        for (int t = 0; t < 4; t++) {
            int c = t * 256 + tid;
            int row = c >> 3, col = c & 7;
            int ar = m0 + row; if (ar >= M) ar = M - 1;
            CP_ASYNC16(aO + row * (ROWE * 2) + col * 16,
                       A + (size_t)ar * DMODEL + k0 + col * 8);
            CP_ASYNC16(bO + row * (ROWE * 2) + col * 16,
                       Bt + (size_t)(n0 + row) * DMODEL + k0 + col * 8);
        }
    };

    // ldmatrix lane addressing
    const int alr = lane & 15;            // A row within 16
    const int alc = lane >> 4;            // A col half (+8 elems)
    const int blr = lane & 7;             // B row within 8
    const int blc = (lane >> 3) & 1;      // B k half

    load_tile(0, 0); CP_COMMIT();
    load_tile(1, 1); CP_COMMIT();
    load_tile(2, 2); CP_COMMIT();

#pragma unroll 1
    for (int kt = 0; kt < KTILES; kt++) {
        const int s = kt & 3;
        CP_WAIT2();                // group for tile kt complete
        __syncthreads();           // all warps done with stage (kt-1) & see stage kt
        // prefetch tile kt+3 into stage (kt+3)&3 == (kt-1)&3 (safe after sync)
        if (kt + 3 < KTILES) load_tile(kt + 3, (kt + 3) & 3);
        CP_COMMIT();               // always commit (empty group keeps accounting)

        const uint32_t aO = sbase + s * 2 * TILEB;
        const uint32_t bO = aO + TILEB;
        const uint32_t aBase = aO + (wm * 64 + alr) * (ROWE * 2) + alc * 16;
        const uint32_t bBase = bO + (wn * 32 + blr) * (ROWE * 2) + blc * 16;
#pragma unroll
        for (int ks = 0; ks < 4; ks++) {
            uint32_t af[4][4], bf[4][2];
#pragma unroll
            for (int mi = 0; mi < 4; mi++)
                LDSM_X4(af[mi], aBase + mi * 16 * (ROWE * 2) + ks * 32);
#pragma unroll
            for (int ni = 0; ni < 4; ni++)
                LDSM_X2(bf[ni], bBase + ni * 8 * (ROWE * 2) + ks * 32);
#pragma unroll
            for (int mi = 0; mi < 4; mi++)
#pragma unroll
                for (int ni = 0; ni < 4; ni++)
                    MMA_16816(acc[mi][ni], af[mi], bf[ni]);
        }
    }

    // ---------------- epilogue ----------------
    const int groupID = lane >> 2, tig = lane & 3;
#pragma unroll
    for (int mi = 0; mi < 4; mi++) {
        const int r0 = m0 + wm * 64 + mi * 16 + groupID;
        const int r1 = r0 + 8;
#pragma unroll
        for (int ni = 0; ni < 4; ni++) {
            const int cb = n0 + wn * 32 + ni * 8 + tig * 2;
            const float* a4 = acc[mi][ni];
            if (EPI == 0) {
                __nv_bfloat16* o = (__nv_bfloat16*)out0;
                float b0v = bias0[cb], b1v = bias0[cb + 1];
                if (r0 < M) {
                    __nv_bfloat162 v;
                    v.x = __float2bfloat16(a4[0] + b0v);
                    v.y = __float2bfloat16(a4[1] + b1v);
                    *reinterpret_cast<__nv_bfloat162*>(o + (size_t)r0 * DMODEL + cb) = v;
                }
                if (r1 < M) {
                    __nv_bfloat162 v;
                    v.x = __float2bfloat16(a4[2] + b0v);
                    v.y = __float2bfloat16(a4[3] + b1v);
                    *reinterpret_cast<__nv_bfloat162*>(o + (size_t)r1 * DMODEL + cb) = v;
                }
            } else if (EPI == 1) {
                float* o0 = (float*)out0;
                float* o1 = (float*)out1;
#pragma unroll
                for (int e = 0; e < 2; e++) {
                    int n = cb + e;
                    float v0 = a4[e], v1 = a4[2 + e];
                    if (n < NOFF) {
                        o0[(size_t)r0 * NOFF + n] = v0 + bias0[n];
                        o0[(size_t)r1 * NOFF + n] = v1 + bias0[n];
                    } else if (n < NCOMB) {
                        o1[(size_t)r0 * NATT + (n - NOFF)] = v0 + bias1[n - NOFF];
                        o1[(size_t)r1 * NATT + (n - NOFF)] = v1 + bias1[n - NOFF];
                    }
                }
            } else {
                float* o = (float*)out0;
#pragma unroll
                for (int e = 0; e < 2; e++) {
                    int n = cb + e;
                    o[(size_t)r0 * DMODEL + n] = resid[(size_t)r0 * DMODEL + n] +
                                                 gamma[n] * (a4[e] + bias0[n]);
                    o[(size_t)r1 * DMODEL + n] = resid[(size_t)r1 * DMODEL + n] +
                                                 gamma[n] * (a4[2 + e] + bias0[n]);
                }
            }
        }
    }
}

// ---------------------------------------------------------------------------
// Deformable sampling + fused softmax: one warp per (b, q, h).
// Branch-free: clamped coords, weight x validity, loads always issued.
// ---------------------------------------------------------------------------
__global__ void __launch_bounds__(256) sample_kernel(
    const float* __restrict__ off, const float* __restrict__ aw,
    const __nv_bfloat16* __restrict__ val, __nv_bfloat16* __restrict__ sam)
{
    constexpr int lvl_h[3] = {112, 56, 28};
    constexpr int lvl_w[3] = {112, 56, 28};
    constexpr int lvl_s[3] = {0, 12544, 15680};

    int warp = (blockIdx.x * blockDim.x + threadIdx.x) >> 5;
    int lane = threadIdx.x & 31;
    if (warp >= BATCH * LQ * NHEAD) return;
    int h  = warp % NHEAD;
    int bq = warp / NHEAD;
    int q  = bq % LQ;
    int b  = bq / LQ;

    const float rx = ((q & 63) + 0.5f) * (1.f / 64.f);
    const float ry = ((q >> 6) + 0.5f) * (1.f / 64.f);

    // prefetch 24 offsets + 12 logits (uniform across warp, float4 loads)
    float offv[24], lg[12];
    {
        const float4* o4 = reinterpret_cast<const float4*>(off + (size_t)warp * 24);
#pragma unroll
        for (int i = 0; i < 6; i++) {
            float4 t = o4[i];
            offv[i * 4 + 0] = t.x; offv[i * 4 + 1] = t.y;
            offv[i * 4 + 2] = t.z; offv[i * 4 + 3] = t.w;
        }
        const float4* a4 = reinterpret_cast<const float4*>(aw + (size_t)warp * 12);
#pragma unroll
        for (int i = 0; i < 3; i++) {
            float4 t = a4[i];
            lg[i * 4 + 0] = t.x; lg[i * 4 + 1] = t.y;
            lg[i * 4 + 2] = t.z; lg[i * 4 + 3] = t.w;
        }
    }

    // softmax over 12 logits
    float mx = -1e30f;
#pragma unroll
    for (int j = 0; j < 12; j++) mx = fmaxf(mx, lg[j]);
    float ssum = 0.f;
#pragma unroll
    for (int j = 0; j < 12; j++) { lg[j] = __expf(lg[j] - mx); ssum += lg[j]; }
    const float sinv = 1.f / ssum;

    float acc0 = 0.f, acc1 = 0.f;

#pragma unroll
    for (int l = 0; l < NLVL; l++) {
        const int h_ = lvl_h[l], w_ = lvl_w[l];
        const float invw = 1.f / (float)w_, invh = 1.f / (float)h_;
        // row base for this (b, level, head): elements
        const __nv_bfloat16* lp = val +
            (((size_t)b * LIN + lvl_s[l]) * NHEAD + h) * HDIM + lane * 2;
#pragma unroll
        for (int p = 0; p < NPT; p++) {
            const float ox = offv[(l * NPT + p) * 2];
            const float oy = offv[(l * NPT + p) * 2 + 1];
            const float a  = lg[l * NPT + p] * sinv;
            const float x = (rx + ox * invw) * (float)w_ - 0.5f;
            const float y = (ry + oy * invh) * (float)h_ - 0.5f;
            const float x0f = floorf(x), y0f = floorf(y);
            const float wx = x - x0f, wy = y - y0f;
            const int x0 = (int)x0f, y0 = (int)y0f;
            const int x1 = x0 + 1, y1 = y0 + 1;

            // validity masks & clamped coords (branch-free)
            const float vx0 = (x0 >= 0 && x0 < w_) ? 1.f : 0.f;
            const float vx1 = (x1 >= 0 && x1 < w_) ? 1.f : 0.f;
            const float vy0 = (y0 >= 0 && y0 < h_) ? 1.f : 0.f;
            const float vy1 = (y1 >= 0 && y1 < h_) ? 1.f : 0.f;
            const int x0c = min(max(x0, 0), w_ - 1);
            const int x1c = min(max(x1, 0), w_ - 1);
            const int y0c = min(max(y0, 0), h_ - 1);
            const int y1c = min(max(y1, 0), h_ - 1);

            const float w00 = (1.f - wx) * (1.f - wy) * a * vx0 * vy0;
            const float w01 = wx * (1.f - wy) * a * vx1 * vy0;
            const float w10 = (1.f - wx) * wy * a * vx0 * vy1;
            const float w11 = wx * wy * a * vx1 * vy1;

            // 4 unconditional gathers (768 elems per token row)
            const __nv_bfloat162 c00 = *reinterpret_cast<const __nv_bfloat162*>(
                lp + ((size_t)y0c * w_ + x0c) * (NHEAD * HDIM));
            const __nv_bfloat162 c01 = *reinterpret_cast<const __nv_bfloat162*>(
                lp + ((size_t)y0c * w_ + x1c) * (NHEAD * HDIM));
            const __nv_bfloat162 c10 = *reinterpret_cast<const __nv_bfloat162*>(
                lp + ((size_t)y1c * w_ + x0c) * (NHEAD * HDIM));
            const __nv_bfloat162 c11 = *reinterpret_cast<const __nv_bfloat162*>(
                lp + ((size_t)y1c * w_ + x1c) * (NHEAD * HDIM));

            float2 f00 = __bfloat1622float2(c00);
            float2 f01 = __bfloat1622float2(c01);
            float2 f10 = __bfloat1622float2(c10);
            float2 f11 = __bfloat1622float2(c11);
            acc0 += w00 * f00.x + w01 * f01.x + w10 * f10.x + w11 * f11.x;
            acc1 += w00 * f00.y + w01 * f01.y + w10 * f10.y + w11 * f11.y;
        }
    }

    size_t so = (size_t)(b * LQ + q) * DMODEL + h * HDIM + lane * 2;
    __nv_bfloat162 r;
    r.x = __float2bfloat16(acc0);
    r.y = __float2bfloat16(acc1);
    *reinterpret_cast<__nv_bfloat162*>(sam + so) = r;
}

// ---------------------------------------------------------------------------
// Launch
// ---------------------------------------------------------------------------
extern "C" void kernel_launch(void* const* d_in, const int* in_sizes, int n_in,
                              void* d_out, int out_size)
{
    const float* query  = (const float*)d_in[0];
    const float* feat   = (const float*)d_in[1];
    const float* ln_q_g = (const float*)d_in[2];
    const float* ln_q_b = (const float*)d_in[3];
    const float* ln_f_g = (const float*)d_in[4];
    const float* ln_f_b = (const float*)d_in[5];
    const float* W_off  = (const float*)d_in[6];
    const float* b_off  = (const float*)d_in[7];
    const float* W_attn = (const float*)d_in[8];
    const float* b_attn = (const float*)d_in[9];
    const float* W_val  = (const float*)d_in[10];
    const float* b_val  = (const float*)d_in[11];
    const float* W_out  = (const float*)d_in[12];
    const float* b_out  = (const float*)d_in[13];
    const float* gamma  = (const float*)d_in[14];
    float* out = (float*)d_out;

    __nv_bfloat16 *p_qln, *p_fln, *p_val, *p_sam, *p_WvalT, *p_WoutT, *p_WcombT;
    float *p_off, *p_aw;
    cudaGetSymbolAddress((void**)&p_qln,   g_qln);
    cudaGetSymbolAddress((void**)&p_fln,   g_fln);
    cudaGetSymbolAddress((void**)&p_val,   g_val);
    cudaGetSymbolAddress((void**)&p_sam,   g_sam);
    cudaGetSymbolAddress((void**)&p_WvalT, g_WvalT);
    cudaGetSymbolAddress((void**)&p_WoutT, g_WoutT);
    cudaGetSymbolAddress((void**)&p_WcombT,g_WcombT);
    cudaGetSymbolAddress((void**)&p_off,   g_off);
    cudaGetSymbolAddress((void**)&p_aw,    g_aw);

    cudaFuncSetAttribute(gemm_mma_kernel<0>, cudaFuncAttributeMaxDynamicSharedMemorySize, GEMM_SMEM);
    cudaFuncSetAttribute(gemm_mma_kernel<1>, cudaFuncAttributeMaxDynamicSharedMemorySize, GEMM_SMEM);
    cudaFuncSetAttribute(gemm_mma_kernel<2>, cudaFuncAttributeMaxDynamicSharedMemorySize, GEMM_SMEM);

    const int Mq = BATCH * LQ;    // 16384
    const int Mf = BATCH * LIN;   // 65856

    // 1. weight transposes -> bf16 [N,K]
    wtransT_kernel<<<dim3(DMODEL / 32, DMODEL / 32), 256>>>(W_val, p_WvalT, DMODEL, DMODEL);
    wtransT_kernel<<<dim3(DMODEL / 32, DMODEL / 32), 256>>>(W_out, p_WoutT, DMODEL, DMODEL);
    wtransC_kernel<<<dim3(DMODEL / 32, NCOMB_PAD / 32), 256>>>(W_off, W_attn, p_WcombT);

    // 2. LayerNorms (warp per row)
    ln_kernel<<<(Mf + 7) / 8, 256>>>(feat, ln_f_g, ln_f_b, p_fln, Mf);
    ln_kernel<<<(Mq + 7) / 8, 256>>>(query, ln_q_g, ln_q_b, p_qln, Mq);

    // 3. value = ln(feat) @ W_val + b_val   (bf16 out)
    gemm_mma_kernel<0><<<dim3((Mf + BM - 1) / BM, DMODEL / BN), 256, GEMM_SMEM>>>(
        p_fln, p_WvalT, Mf, b_val, nullptr, p_val, nullptr, nullptr, nullptr);

    // 4+5. fused offsets+attn logits (split epilogue; softmax fused into sampling)
    gemm_mma_kernel<1><<<dim3(Mq / BM, NCOMB_PAD / BN), 256, GEMM_SMEM>>>(
        p_qln, p_WcombT, Mq, b_off, b_attn, p_off, p_aw, nullptr, nullptr);

    // 6+7. deformable sampling with fused softmax -> g_sam (bf16)
    sample_kernel<<<(Mq * NHEAD) / 8, 256>>>(p_off, p_aw, p_val, p_sam);

    // 8. out = query + gamma * (g_sam @ W_out + b_out)
    gemm_mma_kernel<2><<<dim3(Mq / BM, DMODEL / BN), 256, GEMM_SMEM>>>(
        p_sam, p_WoutT, Mq, b_out, nullptr, out, nullptr, query, gamma);
}

// round 11
// speedup vs baseline: 1.1719x; 1.1719x over previous
#include <cuda_runtime.h>
#include <cuda_bf16.h>
#include <cstdint>

// ---------------------------------------------------------------------------
// Problem constants
// ---------------------------------------------------------------------------
#define BATCH 4
#define DMODEL 768
#define NHEAD 12
#define HDIM 64
#define NLVL 3
#define NPT 4
#define LQ 4096           // 64 x 64 query grid
#define LIN 16464         // 112*112 + 56*56 + 28*28
#define NOFF 288          // NH*NL*NP*2
#define NATT 144          // NH*NL*NP
#define NCOMB 432         // NOFF+NATT
#define NCOMB_PAD 512

// GEMM tiling (R6 configuration: 2-stage, 73.7 KB smem, 2 CTAs/SM)
#define BM 128
#define BN 128
#define BK 64
#define ROWE 72            // bf16 elements per SMEM row (64 + 8 pad) = 144 B
#define KTILES (DMODEL / BK)   // 12
#define TILEB (BM * ROWE * 2)  // 18432 B per matrix-stage
#define GEMM_SMEM (4 * TILEB)  // 73728 B

// ---------------------------------------------------------------------------
// Scratch (device globals; no runtime allocation allowed)
// ---------------------------------------------------------------------------
__device__ __nv_bfloat16 g_qln[(size_t)BATCH * LQ * DMODEL];
__device__ __nv_bfloat16 g_fln[(size_t)BATCH * LIN * DMODEL];
__device__ uint8_t       g_val8[(size_t)BATCH * LIN * DMODEL];   // e4m3 storage
__device__ float         g_off[(size_t)BATCH * LQ * NOFF];
__device__ float         g_aw [(size_t)BATCH * LQ * NATT];
__device__ __nv_bfloat16 g_sam[(size_t)BATCH * LQ * DMODEL];
__device__ __nv_bfloat16 g_WvalT[DMODEL * DMODEL];        // [n][k]
__device__ __nv_bfloat16 g_WoutT[DMODEL * DMODEL];        // [n][k]
__device__ __nv_bfloat16 g_WcombT[NCOMB_PAD * DMODEL];    // [n][k], rows >=432 zero

// ---------------------------------------------------------------------------
// helpers
// ---------------------------------------------------------------------------
__device__ __forceinline__ uint32_t smem_u32(const void* p) {
    uint32_t a;
    asm("{ .reg .u64 t; cvta.to.shared.u64 t, %1; cvt.u32.u64 %0, t; }" : "=r"(a) : "l"(p));
    return a;
}

#define CP_ASYNC16(sp, gp) \
    asm volatile("cp.async.cg.shared.global [%0], [%1], 16;" :: "r"(sp), "l"(gp) : "memory")
#define CP_COMMIT() asm volatile("cp.async.commit_group;" ::: "memory")
#define CP_WAIT1()  asm volatile("cp.async.wait_group 1;" ::: "memory")

#define LDSM_X4(r, addr)                                                      \
    asm volatile("ldmatrix.sync.aligned.m8n8.x4.shared.b16 {%0,%1,%2,%3}, [%4];" \
        : "=r"((r)[0]), "=r"((r)[1]), "=r"((r)[2]), "=r"((r)[3]) : "r"(addr))
#define LDSM_X2(r, addr)                                                      \
    asm volatile("ldmatrix.sync.aligned.m8n8.x2.shared.b16 {%0,%1}, [%2];"    \
        : "=r"((r)[0]), "=r"((r)[1]) : "r"(addr))

#define MMA_16816(c, a, b)                                                    \
    asm volatile("mma.sync.aligned.m16n8k16.row.col.f32.bf16.bf16.f32 "       \
        "{%0,%1,%2,%3}, {%4,%5,%6,%7}, {%8,%9}, {%0,%1,%2,%3};"               \
        : "+f"((c)[0]), "+f"((c)[1]), "+f"((c)[2]), "+f"((c)[3])              \
        : "r"((a)[0]), "r"((a)[1]), "r"((a)[2]), "r"((a)[3]),                 \
          "r"((b)[0]), "r"((b)[1]))

// pack (lo, hi) floats -> e4m3x2 (lo in low byte)
__device__ __forceinline__ uint16_t pack_e4m3x2(float lo, float hi) {
    uint16_t r;
    asm("cvt.rn.satfinite.e4m3x2.f32 %0, %1, %2;" : "=h"(r) : "f"(hi), "f"(lo));
    return r;
}
// e4m3x2 -> float2 (exact via f16x2)
__device__ __forceinline__ float2 unpack_e4m3x2(uint16_t v) {
    uint32_t h2;
    asm("cvt.rn.f16x2.e4m3x2 %0, %1;" : "=r"(h2) : "h"(v));
    __half2 hh = *reinterpret_cast<__half2*>(&h2);
    return __half22float2(hh);
}

// ---------------------------------------------------------------------------
// Tiled transpose fp32 [K,N] -> bf16 [N,K]  (32x32 smem tiles, coalesced)
// ---------------------------------------------------------------------------
__global__ void __launch_bounds__(256) wtransT_kernel(
    const float* __restrict__ W, __nv_bfloat16* __restrict__ Wt, int K, int N)
{
    __shared__ float t[32][33];
    const int kb = blockIdx.x * 32, nb = blockIdx.y * 32;
    const int tx = threadIdx.x & 31, ty = threadIdx.x >> 5;   // 32 x 8
#pragma unroll
    for (int i = 0; i < 32; i += 8) {
        int k = kb + ty + i, n = nb + tx;
        float v = (k < K && n < N) ? W[(size_t)k * N + n] : 0.f;
        t[ty + i][tx] = v;
    }
    __syncthreads();
#pragma unroll
    for (int i = 0; i < 32; i += 8) {
        int n = nb + ty + i, k = kb + tx;
        if (n < N && k < K)
            Wt[(size_t)n * K + k] = __float2bfloat16(t[tx][ty + i]);
    }
}

// combined off+attn transpose into padded [NCOMB_PAD, K]; rows >= NCOMB get 0
__global__ void __launch_bounds__(256) wtransC_kernel(
    const float* __restrict__ Woff, const float* __restrict__ Wattn,
    __nv_bfloat16* __restrict__ Wt)
{
    __shared__ float t[32][33];
    const int kb = blockIdx.x * 32, nb = blockIdx.y * 32;
    const int tx = threadIdx.x & 31, ty = threadIdx.x >> 5;
#pragma unroll
    for (int i = 0; i < 32; i += 8) {
        int k = kb + ty + i, n = nb + tx;
        float v = 0.f;
        if (k < DMODEL) {
            if (n < NOFF) v = Woff[(size_t)k * NOFF + n];
            else if (n < NCOMB) v = Wattn[(size_t)k * NATT + (n - NOFF)];
        }
        t[ty + i][tx] = v;
    }
    __syncthreads();
#pragma unroll
    for (int i = 0; i < 32; i += 8) {
        int n = nb + ty + i, k = kb + tx;
        if (n < NCOMB_PAD && k < DMODEL)
            Wt[(size_t)n * DMODEL + k] = __float2bfloat16(t[tx][ty + i]);
    }
}

// ---------------------------------------------------------------------------
// LayerNorm: one warp per row (768), float4 loads, shuffle-only reduction
// ---------------------------------------------------------------------------
__global__ void __launch_bounds__(256) ln_kernel(
    const float* __restrict__ x, const float* __restrict__ g,
    const float* __restrict__ b, __nv_bfloat16* __restrict__ out, int nrows)
{
    const int row = blockIdx.x * 8 + (threadIdx.x >> 5);
    const int lane = threadIdx.x & 31;
    if (row >= nrows) return;
    const float4* xr = reinterpret_cast<const float4*>(x + (size_t)row * DMODEL);
    float4 v[6];
    float s = 0.f, s2 = 0.f;
#pragma unroll
    for (int i = 0; i < 6; i++) {
        v[i] = xr[i * 32 + lane];
        s  += v[i].x + v[i].y + v[i].z + v[i].w;
        s2 += v[i].x * v[i].x + v[i].y * v[i].y + v[i].z * v[i].z + v[i].w * v[i].w;
    }
#pragma unroll
    for (int o = 16; o > 0; o >>= 1) {
        s  += __shfl_xor_sync(0xFFFFFFFFu, s,  o);
        s2 += __shfl_xor_sync(0xFFFFFFFFu, s2, o);
    }
    const float mean = s * (1.f / DMODEL);
    const float var  = s2 * (1.f / DMODEL) - mean * mean;
    const float rstd = rsqrtf(var + 1e-6f);
    const float4* gp = reinterpret_cast<const float4*>(g);
    const float4* bp = reinterpret_cast<const float4*>(b);
    uint2* o = reinterpret_cast<uint2*>(out + (size_t)row * DMODEL);
#pragma unroll
    for (int i = 0; i < 6; i++) {
        float4 gv = gp[i * 32 + lane];
        float4 bv = bp[i * 32 + lane];
        __nv_bfloat162 p0, p1;
        p0.x = __float2bfloat16((v[i].x - mean) * rstd * gv.x + bv.x);
        p0.y = __float2bfloat16((v[i].y - mean) * rstd * gv.y + bv.y);
        p1.x = __float2bfloat16((v[i].z - mean) * rstd * gv.z + bv.z);
        p1.y = __float2bfloat16((v[i].w - mean) * rstd * gv.w + bv.w);
        uint2 w;
        w.x = *reinterpret_cast<uint32_t*>(&p0);
        w.y = *reinterpret_cast<uint32_t*>(&p1);
        o[i * 32 + lane] = w;
    }
}

// ---------------------------------------------------------------------------
// mma.sync bf16 GEMM (R6 config): CTA 128x128, 8 warps (2x4), warp 64x32,
// k-chunks of 64, cp.async double buffer, ldmatrix fragments, fp32 accum.
// EPI 0: e4m3 C (value)   EPI 1: split off(288)/attn(144) float
// EPI 2: float out = resid + gamma*(acc+bias)
// ---------------------------------------------------------------------------
template <int EPI>
__global__ void __launch_bounds__(256) gemm_mma_kernel(
    const __nv_bfloat16* __restrict__ A, const __nv_bfloat16* __restrict__ Bt,
    int M, const float* __restrict__ bias0, const float* __restrict__ bias1,
    void* __restrict__ out0, void* __restrict__ out1,
    const float* __restrict__ resid, const float* __restrict__ gamma)
{
    extern __shared__ char smem[];
    const uint32_t sbase = smem_u32(smem);

    const int tid  = threadIdx.x;
    const int wid  = tid >> 5;
    const int lane = tid & 31;
    const int wm   = wid >> 2;        // 0..1
    const int wn   = wid & 3;         // 0..3
    const int m0   = blockIdx.x * BM;
    const int n0   = blockIdx.y * BN;

    // layout: [A0][B0][A1][B1], each TILEB bytes
    const uint32_t aOff[2] = {sbase, sbase + 2 * TILEB};
    const uint32_t bOff[2] = {sbase + TILEB, sbase + 3 * TILEB};

    float acc[4][4][4];
#pragma unroll
    for (int mi = 0; mi < 4; mi++)
#pragma unroll
        for (int ni = 0; ni < 4; ni++)
#pragma unroll
            for (int r = 0; r < 4; r++) acc[mi][ni][r] = 0.f;

    // 1024 16B-chunks per matrix-tile, 4 per thread
    auto load_tile = [&](int kt, int s) {
        const int k0 = kt * BK;
#pragma unroll
        for (int t = 0; t < 4; t++) {
            int c = t * 256 + tid;
            int row = c >> 3, col = c & 7;
            int ar = m0 + row; if (ar >= M) ar = M - 1;
            CP_ASYNC16(aOff[s] + row * (ROWE * 2) + col * 16,
                       A + (size_t)ar * DMODEL + k0 + col * 8);
            CP_ASYNC16(bOff[s] + row * (ROWE * 2) + col * 16,
                       Bt + (size_t)(n0 + row) * DMODEL + k0 + col * 8);
        }
    };

    // ldmatrix lane addressing
    const int alr = lane & 15;            // A row within 16
    const int alc = lane >> 4;            // A col half (+8 elems)
    const int blr = lane & 7;             // B row within 8
    const int blc = (lane >> 3) & 1;      // B k half

    load_tile(0, 0);
    CP_COMMIT();

#pragma unroll 1
    for (int kt = 0; kt < KTILES; kt++) {
        const int s = kt & 1;
        if (kt + 1 < KTILES) load_tile(kt + 1, (kt + 1) & 1);
        CP_COMMIT();
        CP_WAIT1();
        __syncthreads();

        const uint32_t aBase = aOff[s] + (wm * 64 + alr) * (ROWE * 2) + alc * 16;
        const uint32_t bBase = bOff[s] + (wn * 32 + blr) * (ROWE * 2) + blc * 16;
#pragma unroll
        for (int ks = 0; ks < 4; ks++) {
            uint32_t af[4][4], bf[4][2];
#pragma unroll
            for (int mi = 0; mi < 4; mi++)
                LDSM_X4(af[mi], aBase + mi * 16 * (ROWE * 2) + ks * 32);
#pragma unroll
            for (int ni = 0; ni < 4; ni++)
                LDSM_X2(bf[ni], bBase + ni * 8 * (ROWE * 2) + ks * 32);
#pragma unroll
            for (int mi = 0; mi < 4; mi++)
#pragma unroll
                for (int ni = 0; ni < 4; ni++)
                    MMA_16816(acc[mi][ni], af[mi], bf[ni]);
        }
        __syncthreads();
    }

    // ---------------- epilogue ----------------
    const int groupID = lane >> 2, tig = lane & 3;
#pragma unroll
    for (int mi = 0; mi < 4; mi++) {
        const int r0 = m0 + wm * 64 + mi * 16 + groupID;
        const int r1 = r0 + 8;
#pragma unroll
        for (int ni = 0; ni < 4; ni++) {
            const int cb = n0 + wn * 32 + ni * 8 + tig * 2;
            const float* a4 = acc[mi][ni];
            if (EPI == 0) {
                uint8_t* o = (uint8_t*)out0;
                float b0v = bias0[cb], b1v = bias0[cb + 1];
                if (r0 < M)
                    *reinterpret_cast<uint16_t*>(o + (size_t)r0 * DMODEL + cb) =
                        pack_e4m3x2(a4[0] + b0v, a4[1] + b1v);
                if (r1 < M)
                    *reinterpret_cast<uint16_t*>(o + (size_t)r1 * DMODEL + cb) =
                        pack_e4m3x2(a4[2] + b0v, a4[3] + b1v);
            } else if (EPI == 1) {
                float* o0 = (float*)out0;
                float* o1 = (float*)out1;
#pragma unroll
                for (int e = 0; e < 2; e++) {
                    int n = cb + e;
                    float v0 = a4[e], v1 = a4[2 + e];
                    if (n < NOFF) {
                        o0[(size_t)r0 * NOFF + n] = v0 + bias0[n];
                        o0[(size_t)r1 * NOFF + n] = v1 + bias0[n];
                    } else if (n < NCOMB) {
                        o1[(size_t)r0 * NATT + (n - NOFF)] = v0 + bias1[n - NOFF];
                        o1[(size_t)r1 * NATT + (n - NOFF)] = v1 + bias1[n - NOFF];
                    }
                }
            } else {
                float* o = (float*)out0;
#pragma unroll
                for (int e = 0; e < 2; e++) {
                    int n = cb + e;
                    o[(size_t)r0 * DMODEL + n] = resid[(size_t)r0 * DMODEL + n] +
                                                 gamma[n] * (a4[e] + bias0[n]);
                    o[(size_t)r1 * DMODEL + n] = resid[(size_t)r1 * DMODEL + n] +
                                                 gamma[n] * (a4[2 + e] + bias0[n]);
                }
            }
        }
    }
}

// ---------------------------------------------------------------------------
// Deformable sampling with fused softmax: one warp per (b, q, h).
// val stored e4m3 (half the gather bytes); accumulate fp32; sam out bf16.
// ---------------------------------------------------------------------------
__global__ void __launch_bounds__(256) sample_kernel(
    const float* __restrict__ off, const float* __restrict__ aw,
    const uint8_t* __restrict__ val, __nv_bfloat16* __restrict__ sam)
{
    constexpr int lvl_h[3] = {112, 56, 28};
    constexpr int lvl_w[3] = {112, 56, 28};
    constexpr int lvl_s[3] = {0, 12544, 15680};

    int warp = (blockIdx.x * blockDim.x + threadIdx.x) >> 5;
    int lane = threadIdx.x & 31;
    if (warp >= BATCH * LQ * NHEAD) return;
    int h  = warp % NHEAD;
    int bq = warp / NHEAD;
    int q  = bq % LQ;
    int b  = bq / LQ;

    float rx = ((q & 63) + 0.5f) * (1.f / 64.f);
    float ry = ((q >> 6) + 0.5f) * (1.f / 64.f);

    const float* offp = off + (size_t)warp * (NLVL * NPT * 2);
    const float* awp  = aw  + (size_t)warp * (NLVL * NPT);

    // softmax over 12 logits (uniform across warp; broadcast loads)
    float lg[12];
    float mx = -1e30f;
#pragma unroll
    for (int j = 0; j < 12; j++) { lg[j] = awp[j]; mx = fmaxf(mx, lg[j]); }
    float ssum = 0.f;
#pragma unroll
    for (int j = 0; j < 12; j++) { lg[j] = __expf(lg[j] - mx); ssum += lg[j]; }
    const float sinv = 1.f / ssum;

    float acc0 = 0.f, acc1 = 0.f;

#pragma unroll
    for (int l = 0; l < NLVL; l++) {
        const int h_ = lvl_h[l], w_ = lvl_w[l], st = lvl_s[l];
        const float invw = 1.f / (float)w_, invh = 1.f / (float)h_;
#pragma unroll
        for (int p = 0; p < NPT; p++) {
            float ox = offp[(l * NPT + p) * 2];
            float oy = offp[(l * NPT + p) * 2 + 1];
            float a  = lg[l * NPT + p] * sinv;
            float x = (rx + ox * invw) * (float)w_ - 0.5f;
            float y = (ry + oy * invh) * (float)h_ - 0.5f;
            float x0f = floorf(x), y0f = floorf(y);
            float wx = x - x0f, wy = y - y0f;
            int x0 = (int)x0f, y0 = (int)y0f;
            float w00 = (1.f - wx) * (1.f - wy) * a;
            float w01 = wx * (1.f - wy) * a;
            float w10 = (1.f - wx) * wy * a;
            float w11 = wx * wy * a;

            const int xs[4] = {x0, x0 + 1, x0, x0 + 1};
            const int ys[4] = {y0, y0, y0 + 1, y0 + 1};
            const float ws[4] = {w00, w01, w10, w11};
#pragma unroll
            for (int c = 0; c < 4; c++) {
                int xi = xs[c], yi = ys[c];
                if (xi >= 0 && xi < w_ && yi >= 0 && yi < h_) {
                    size_t base = (((size_t)b * LIN + st + (size_t)yi * w_ + xi) * NHEAD + h)
                                  * HDIM + lane * 2;
                    uint16_t v2 = *reinterpret_cast<const uint16_t*>(val + base);
                    float2 f = unpack_e4m3x2(v2);
                    acc0 += ws[c] * f.x;
                    acc1 += ws[c] * f.y;
                }
            }
        }
    }

    size_t so = (size_t)(b * LQ + q) * DMODEL + h * HDIM + lane * 2;
    __nv_bfloat162 r;
    r.x = __float2bfloat16(acc0);
    r.y = __float2bfloat16(acc1);
    *reinterpret_cast<__nv_bfloat162*>(sam + so) = r;
}

// ---------------------------------------------------------------------------
// Launch
// ---------------------------------------------------------------------------
extern "C" void kernel_launch(void* const* d_in, const int* in_sizes, int n_in,
                              void* d_out, int out_size)
{
    const float* query  = (const float*)d_in[0];
    const float* feat   = (const float*)d_in[1];
    const float* ln_q_g = (const float*)d_in[2];
    const float* ln_q_b = (const float*)d_in[3];
    const float* ln_f_g = (const float*)d_in[4];
    const float* ln_f_b = (const float*)d_in[5];
    const float* W_off  = (const float*)d_in[6];
    const float* b_off  = (const float*)d_in[7];
    const float* W_attn = (const float*)d_in[8];
    const float* b_attn = (const float*)d_in[9];
    const float* W_val  = (const float*)d_in[10];
    const float* b_val  = (const float*)d_in[11];
    const float* W_out  = (const float*)d_in[12];
    const float* b_out  = (const float*)d_in[13];
    const float* gamma  = (const float*)d_in[14];
    float* out = (float*)d_out;

    __nv_bfloat16 *p_qln, *p_fln, *p_sam, *p_WvalT, *p_WoutT, *p_WcombT;
    uint8_t *p_val8;
    float *p_off, *p_aw;
    cudaGetSymbolAddress((void**)&p_qln,   g_qln);
    cudaGetSymbolAddress((void**)&p_fln,   g_fln);
    cudaGetSymbolAddress((void**)&p_val8,  g_val8);
    cudaGetSymbolAddress((void**)&p_sam,   g_sam);
    cudaGetSymbolAddress((void**)&p_WvalT, g_WvalT);
    cudaGetSymbolAddress((void**)&p_WoutT, g_WoutT);
    cudaGetSymbolAddress((void**)&p_WcombT,g_WcombT);
    cudaGetSymbolAddress((void**)&p_off,   g_off);
    cudaGetSymbolAddress((void**)&p_aw,    g_aw);

    cudaFuncSetAttribute(gemm_mma_kernel<0>, cudaFuncAttributeMaxDynamicSharedMemorySize, GEMM_SMEM);
    cudaFuncSetAttribute(gemm_mma_kernel<1>, cudaFuncAttributeMaxDynamicSharedMemorySize, GEMM_SMEM);
    cudaFuncSetAttribute(gemm_mma_kernel<2>, cudaFuncAttributeMaxDynamicSharedMemorySize, GEMM_SMEM);

    const int Mq = BATCH * LQ;    // 16384
    const int Mf = BATCH * LIN;   // 65856

    // 1. weight transposes -> bf16 [N,K] (tiled, coalesced)
    wtransT_kernel<<<dim3(DMODEL / 32, DMODEL / 32), 256>>>(W_val, p_WvalT, DMODEL, DMODEL);
    wtransT_kernel<<<dim3(DMODEL / 32, DMODEL / 32), 256>>>(W_out, p_WoutT, DMODEL, DMODEL);
    wtransC_kernel<<<dim3(DMODEL / 32, NCOMB_PAD / 32), 256>>>(W_off, W_attn, p_WcombT);

    // 2. LayerNorms (warp per row)
    ln_kernel<<<(Mf + 7) / 8, 256>>>(feat, ln_f_g, ln_f_b, p_fln, Mf);
    ln_kernel<<<(Mq + 7) / 8, 256>>>(query, ln_q_g, ln_q_b, p_qln, Mq);

    // 3. value = ln(feat) @ W_val + b_val   (bf16 compute -> e4m3 storage)
    gemm_mma_kernel<0><<<dim3((Mf + BM - 1) / BM, DMODEL / BN), 256, GEMM_SMEM>>>(
        p_fln, p_WvalT, Mf, b_val, nullptr, p_val8, nullptr, nullptr, nullptr);

    // 4+5. fused offsets+attn logits (split epilogue; softmax fused into sampling)
    gemm_mma_kernel<1><<<dim3(Mq / BM, NCOMB_PAD / BN), 256, GEMM_SMEM>>>(
        p_qln, p_WcombT, Mq, b_off, b_attn, p_off, p_aw, nullptr, nullptr);

    // 6+7. deformable sampling with fused softmax -> g_sam (bf16)
    sample_kernel<<<(Mq * NHEAD) / 8, 256>>>(p_off, p_aw, p_val8, p_sam);

    // 8. out = query + gamma * (g_sam @ W_out + b_out)
    gemm_mma_kernel<2><<<dim3(Mq / BM, DMODEL / BN), 256, GEMM_SMEM>>>(
        p_sam, p_WoutT, Mq, b_out, nullptr, out, nullptr, query, gamma);
}

// round 14
// speedup vs baseline: 1.4468x; 1.2345x over previous
#include <cuda_runtime.h>
#include <cuda_bf16.h>
#include <cstdint>

// ---------------------------------------------------------------------------
// Problem constants
// ---------------------------------------------------------------------------
#define BATCH 4
#define DMODEL 768
#define NHEAD 12
#define HDIM 64
#define NLVL 3
#define NPT 4
#define LQ 4096           // 64 x 64 query grid
#define LIN 16464         // 112*112 + 56*56 + 28*28
#define NOFF 288          // NH*NL*NP*2
#define NATT 144          // NH*NL*NP
#define NCOMB 432         // NOFF+NATT
#define NCOMB_PAD 512

// GEMM tiling (R6 configuration: 2-stage, 73.7 KB smem, 2 CTAs/SM)
#define BM 128
#define BN 128
#define BK 64
#define ROWE 72            // bf16 elements per SMEM row (64 + 8 pad) = 144 B
#define KTILES (DMODEL / BK)   // 12
#define TILEB (BM * ROWE * 2)  // 18432 B per matrix-stage
#define GEMM_SMEM (4 * TILEB)  // 73728 B

// ---------------------------------------------------------------------------
// Scratch (device globals; no runtime allocation allowed)
// ---------------------------------------------------------------------------
__device__ __nv_bfloat16 g_qln[(size_t)BATCH * LQ * DMODEL];
__device__ __nv_bfloat16 g_fln[(size_t)BATCH * LIN * DMODEL];
__device__ uint8_t       g_val8[(size_t)BATCH * LIN * DMODEL];   // e4m3 storage
__device__ float         g_off[(size_t)BATCH * LQ * NOFF];
__device__ float         g_aw [(size_t)BATCH * LQ * NATT];
__device__ __nv_bfloat16 g_sam[(size_t)BATCH * LQ * DMODEL];
__device__ __nv_bfloat16 g_WvalT[DMODEL * DMODEL];        // [n][k]
__device__ __nv_bfloat16 g_WoutT[DMODEL * DMODEL];        // [n][k]
__device__ __nv_bfloat16 g_WcombT[NCOMB_PAD * DMODEL];    // [n][k], rows >=432 zero

// ---------------------------------------------------------------------------
// helpers
// ---------------------------------------------------------------------------
__device__ __forceinline__ uint32_t smem_u32(const void* p) {
    uint32_t a;
    asm("{ .reg .u64 t; cvta.to.shared.u64 t, %1; cvt.u32.u64 %0, t; }" : "=r"(a) : "l"(p));
    return a;
}

#define CP_ASYNC16(sp, gp) \
    asm volatile("cp.async.cg.shared.global [%0], [%1], 16;" :: "r"(sp), "l"(gp) : "memory")
#define CP_COMMIT() asm volatile("cp.async.commit_group;" ::: "memory")
#define CP_WAIT1()  asm volatile("cp.async.wait_group 1;" ::: "memory")

#define LDSM_X4(r, addr)                                                      \
    asm volatile("ldmatrix.sync.aligned.m8n8.x4.shared.b16 {%0,%1,%2,%3}, [%4];" \
        : "=r"((r)[0]), "=r"((r)[1]), "=r"((r)[2]), "=r"((r)[3]) : "r"(addr))
#define LDSM_X2(r, addr)                                                      \
    asm volatile("ldmatrix.sync.aligned.m8n8.x2.shared.b16 {%0,%1}, [%2];"    \
        : "=r"((r)[0]), "=r"((r)[1]) : "r"(addr))

#define MMA_16816(c, a, b)                                                    \
    asm volatile("mma.sync.aligned.m16n8k16.row.col.f32.bf16.bf16.f32 "       \
        "{%0,%1,%2,%3}, {%4,%5,%6,%7}, {%8,%9}, {%0,%1,%2,%3};"               \
        : "+f"((c)[0]), "+f"((c)[1]), "+f"((c)[2]), "+f"((c)[3])              \
        : "r"((a)[0]), "r"((a)[1]), "r"((a)[2]), "r"((a)[3]),                 \
          "r"((b)[0]), "r"((b)[1]))

// pack (lo, hi) floats -> e4m3x2 (lo in low byte)
__device__ __forceinline__ uint16_t pack_e4m3x2(float lo, float hi) {
    uint16_t r;
    asm("cvt.rn.satfinite.e4m3x2.f32 %0, %1, %2;" : "=h"(r) : "f"(hi), "f"(lo));
    return r;
}
// e4m3x2 -> float2 (exact via f16x2)
__device__ __forceinline__ float2 unpack_e4m3x2(uint16_t v) {
    uint32_t h2;
    asm("cvt.rn.f16x2.e4m3x2 %0, %1;" : "=r"(h2) : "h"(v));
    __half2 hh = *reinterpret_cast<__half2*>(&h2);
    return __half22float2(hh);
}
// 4 e4m3 bytes -> float4
__device__ __forceinline__ float4 unpack4_e4m3(uint32_t v) {
    float2 lo = unpack_e4m3x2((uint16_t)(v & 0xFFFFu));
    float2 hi = unpack_e4m3x2((uint16_t)(v >> 16));
    return make_float4(lo.x, lo.y, hi.x, hi.y);
}

// ---------------------------------------------------------------------------
// Tiled transpose fp32 [K,N] -> bf16 [N,K]  (32x32 smem tiles, coalesced)
// ---------------------------------------------------------------------------
__global__ void __launch_bounds__(256) wtransT_kernel(
    const float* __restrict__ W, __nv_bfloat16* __restrict__ Wt, int K, int N)
{
    __shared__ float t[32][33];
    const int kb = blockIdx.x * 32, nb = blockIdx.y * 32;
    const int tx = threadIdx.x & 31, ty = threadIdx.x >> 5;   // 32 x 8
#pragma unroll
    for (int i = 0; i < 32; i += 8) {
        int k = kb + ty + i, n = nb + tx;
        float v = (k < K && n < N) ? W[(size_t)k * N + n] : 0.f;
        t[ty + i][tx] = v;
    }
    __syncthreads();
#pragma unroll
    for (int i = 0; i < 32; i += 8) {
        int n = nb + ty + i, k = kb + tx;
        if (n < N && k < K)
            Wt[(size_t)n * K + k] = __float2bfloat16(t[tx][ty + i]);
    }
}

// combined off+attn transpose into padded [NCOMB_PAD, K]; rows >= NCOMB get 0
__global__ void __launch_bounds__(256) wtransC_kernel(
    const float* __restrict__ Woff, const float* __restrict__ Wattn,
    __nv_bfloat16* __restrict__ Wt)
{
    __shared__ float t[32][33];
    const int kb = blockIdx.x * 32, nb = blockIdx.y * 32;
    const int tx = threadIdx.x & 31, ty = threadIdx.x >> 5;
#pragma unroll
    for (int i = 0; i < 32; i += 8) {
        int k = kb + ty + i, n = nb + tx;
        float v = 0.f;
        if (k < DMODEL) {
            if (n < NOFF) v = Woff[(size_t)k * NOFF + n];
            else if (n < NCOMB) v = Wattn[(size_t)k * NATT + (n - NOFF)];
        }
        t[ty + i][tx] = v;
    }
    __syncthreads();
#pragma unroll
    for (int i = 0; i < 32; i += 8) {
        int n = nb + ty + i, k = kb + tx;
        if (n < NCOMB_PAD && k < DMODEL)
            Wt[(size_t)n * DMODEL + k] = __float2bfloat16(t[tx][ty + i]);
    }
}

// ---------------------------------------------------------------------------
// LayerNorm: one warp per row (768), float4 loads, shuffle-only reduction
// ---------------------------------------------------------------------------
__global__ void __launch_bounds__(256) ln_kernel(
    const float* __restrict__ x, const float* __restrict__ g,
    const float* __restrict__ b, __nv_bfloat16* __restrict__ out, int nrows)
{
    const int row = blockIdx.x * 8 + (threadIdx.x >> 5);
    const int lane = threadIdx.x & 31;
    if (row >= nrows) return;
    const float4* xr = reinterpret_cast<const float4*>(x + (size_t)row * DMODEL);
    float4 v[6];
    float s = 0.f, s2 = 0.f;
#pragma unroll
    for (int i = 0; i < 6; i++) {
        v[i] = xr[i * 32 + lane];
        s  += v[i].x + v[i].y + v[i].z + v[i].w;
        s2 += v[i].x * v[i].x + v[i].y * v[i].y + v[i].z * v[i].z + v[i].w * v[i].w;
    }
#pragma unroll
    for (int o = 16; o > 0; o >>= 1) {
        s  += __shfl_xor_sync(0xFFFFFFFFu, s,  o);
        s2 += __shfl_xor_sync(0xFFFFFFFFu, s2, o);
    }
    const float mean = s * (1.f / DMODEL);
    const float var  = s2 * (1.f / DMODEL) - mean * mean;
    const float rstd = rsqrtf(var + 1e-6f);
    const float4* gp = reinterpret_cast<const float4*>(g);
    const float4* bp = reinterpret_cast<const float4*>(b);
    uint2* o = reinterpret_cast<uint2*>(out + (size_t)row * DMODEL);
#pragma unroll
    for (int i = 0; i < 6; i++) {
        float4 gv = gp[i * 32 + lane];
        float4 bv = bp[i * 32 + lane];
        __nv_bfloat162 p0, p1;
        p0.x = __float2bfloat16((v[i].x - mean) * rstd * gv.x + bv.x);
        p0.y = __float2bfloat16((v[i].y - mean) * rstd * gv.y + bv.y);
        p1.x = __float2bfloat16((v[i].z - mean) * rstd * gv.z + bv.z);
        p1.y = __float2bfloat16((v[i].w - mean) * rstd * gv.w + bv.w);
        uint2 w;
        w.x = *reinterpret_cast<uint32_t*>(&p0);
        w.y = *reinterpret_cast<uint32_t*>(&p1);
        o[i * 32 + lane] = w;
    }
}

// ---------------------------------------------------------------------------
// mma.sync bf16 GEMM (R6 config): CTA 128x128, 8 warps (2x4), warp 64x32,
// k-chunks of 64, cp.async double buffer, ldmatrix fragments, fp32 accum.
// EPI 0: e4m3 C (value)   EPI 1: split off(288)/attn(144) float
// EPI 2: float out = resid + gamma*(acc+bias)
// ---------------------------------------------------------------------------
template <int EPI>
__global__ void __launch_bounds__(256) gemm_mma_kernel(
    const __nv_bfloat16* __restrict__ A, const __nv_bfloat16* __restrict__ Bt,
    int M, const float* __restrict__ bias0, const float* __restrict__ bias1,
    void* __restrict__ out0, void* __restrict__ out1,
    const float* __restrict__ resid, const float* __restrict__ gamma)
{
    extern __shared__ char smem[];
    const uint32_t sbase = smem_u32(smem);

    const int tid  = threadIdx.x;
    const int wid  = tid >> 5;
    const int lane = tid & 31;
    const int wm   = wid >> 2;        // 0..1
    const int wn   = wid & 3;         // 0..3
    const int m0   = blockIdx.x * BM;
    const int n0   = blockIdx.y * BN;

    // layout: [A0][B0][A1][B1], each TILEB bytes
    const uint32_t aOff[2] = {sbase, sbase + 2 * TILEB};
    const uint32_t bOff[2] = {sbase + TILEB, sbase + 3 * TILEB};

    float acc[4][4][4];
#pragma unroll
    for (int mi = 0; mi < 4; mi++)
#pragma unroll
        for (int ni = 0; ni < 4; ni++)
#pragma unroll
            for (int r = 0; r < 4; r++) acc[mi][ni][r] = 0.f;

    // 1024 16B-chunks per matrix-tile, 4 per thread
    auto load_tile = [&](int kt, int s) {
        const int k0 = kt * BK;
#pragma unroll
        for (int t = 0; t < 4; t++) {
            int c = t * 256 + tid;
            int row = c >> 3, col = c & 7;
            int ar = m0 + row; if (ar >= M) ar = M - 1;
            CP_ASYNC16(aOff[s] + row * (ROWE * 2) + col * 16,
                       A + (size_t)ar * DMODEL + k0 + col * 8);
            CP_ASYNC16(bOff[s] + row * (ROWE * 2) + col * 16,
                       Bt + (size_t)(n0 + row) * DMODEL + k0 + col * 8);
        }
    };

    // ldmatrix lane addressing
    const int alr = lane & 15;            // A row within 16
    const int alc = lane >> 4;            // A col half (+8 elems)
    const int blr = lane & 7;             // B row within 8
    const int blc = (lane >> 3) & 1;      // B k half

    load_tile(0, 0);
    CP_COMMIT();

#pragma unroll 1
    for (int kt = 0; kt < KTILES; kt++) {
        const int s = kt & 1;
        if (kt + 1 < KTILES) load_tile(kt + 1, (kt + 1) & 1);
        CP_COMMIT();
        CP_WAIT1();
        __syncthreads();

        const uint32_t aBase = aOff[s] + (wm * 64 + alr) * (ROWE * 2) + alc * 16;
        const uint32_t bBase = bOff[s] + (wn * 32 + blr) * (ROWE * 2) + blc * 16;
#pragma unroll
        for (int ks = 0; ks < 4; ks++) {
            uint32_t af[4][4], bf[4][2];
#pragma unroll
            for (int mi = 0; mi < 4; mi++)
                LDSM_X4(af[mi], aBase + mi * 16 * (ROWE * 2) + ks * 32);
#pragma unroll
            for (int ni = 0; ni < 4; ni++)
                LDSM_X2(bf[ni], bBase + ni * 8 * (ROWE * 2) + ks * 32);
#pragma unroll
            for (int mi = 0; mi < 4; mi++)
#pragma unroll
                for (int ni = 0; ni < 4; ni++)
                    MMA_16816(acc[mi][ni], af[mi], bf[ni]);
        }
        __syncthreads();
    }

    // ---------------- epilogue ----------------
    const int groupID = lane >> 2, tig = lane & 3;
#pragma unroll
    for (int mi = 0; mi < 4; mi++) {
        const int r0 = m0 + wm * 64 + mi * 16 + groupID;
        const int r1 = r0 + 8;
#pragma unroll
        for (int ni = 0; ni < 4; ni++) {
            const int cb = n0 + wn * 32 + ni * 8 + tig * 2;
            const float* a4 = acc[mi][ni];
            if (EPI == 0) {
                uint8_t* o = (uint8_t*)out0;
                float b0v = bias0[cb], b1v = bias0[cb + 1];
                if (r0 < M)
                    *reinterpret_cast<uint16_t*>(o + (size_t)r0 * DMODEL + cb) =
                        pack_e4m3x2(a4[0] + b0v, a4[1] + b1v);
                if (r1 < M)
                    *reinterpret_cast<uint16_t*>(o + (size_t)r1 * DMODEL + cb) =
                        pack_e4m3x2(a4[2] + b0v, a4[3] + b1v);
            } else if (EPI == 1) {
                float* o0 = (float*)out0;
                float* o1 = (float*)out1;
#pragma unroll
                for (int e = 0; e < 2; e++) {
                    int n = cb + e;
                    float v0 = a4[e], v1 = a4[2 + e];
                    if (n < NOFF) {
                        o0[(size_t)r0 * NOFF + n] = v0 + bias0[n];
                        o0[(size_t)r1 * NOFF + n] = v1 + bias0[n];
                    } else if (n < NCOMB) {
                        o1[(size_t)r0 * NATT + (n - NOFF)] = v0 + bias1[n - NOFF];
                        o1[(size_t)r1 * NATT + (n - NOFF)] = v1 + bias1[n - NOFF];
                    }
                }
            } else {
                float* o = (float*)out0;
#pragma unroll
                for (int e = 0; e < 2; e++) {
                    int n = cb + e;
                    o[(size_t)r0 * DMODEL + n] = resid[(size_t)r0 * DMODEL + n] +
                                                 gamma[n] * (a4[e] + bias0[n]);
                    o[(size_t)r1 * DMODEL + n] = resid[(size_t)r1 * DMODEL + n] +
                                                 gamma[n] * (a4[2 + e] + bias0[n]);
                }
            }
        }
    }
}

// ---------------------------------------------------------------------------
// Deformable sampling + fused softmax.
// 4 units per warp: 8 lanes per (b,q,h), each lane owns 8 of 64 dims.
// Branch-free corners, 32-bit addressing, fp8 value gathers.
// ---------------------------------------------------------------------------
__global__ void __launch_bounds__(256) sample_kernel(
    const float* __restrict__ off, const float* __restrict__ aw,
    const uint8_t* __restrict__ val, __nv_bfloat16* __restrict__ sam)
{
    constexpr int lvl_h[3] = {112, 56, 28};
    constexpr int lvl_w[3] = {112, 56, 28};
    constexpr int lvl_s[3] = {0, 12544, 15680};

    const int warp = (blockIdx.x * blockDim.x + threadIdx.x) >> 5;
    const int lane = threadIdx.x & 31;
    const int grp  = lane >> 3;          // unit within warp (0..3)
    const int ln8  = lane & 7;           // lane within unit, 8 dims each
    const int unit = warp * 4 + grp;     // (b*LQ+q)*NHEAD + h
    if (unit >= BATCH * LQ * NHEAD) return;

    const int h  = unit % NHEAD;
    const int bq = unit / NHEAD;
    const int q  = bq & (LQ - 1);
    const int b  = bq >> 12;

    const float rx = ((q & 63) + 0.5f) * (1.f / 64.f);
    const float ry = ((q >> 6) + 0.5f) * (1.f / 64.f);

    // per-unit offsets + logits (broadcast within 8-lane group)
    float offv[24], lg[12];
    {
        const float4* o4 = reinterpret_cast<const float4*>(off + (size_t)unit * 24);
#pragma unroll
        for (int i = 0; i < 6; i++) {
            float4 t = o4[i];
            offv[4 * i + 0] = t.x; offv[4 * i + 1] = t.y;
            offv[4 * i + 2] = t.z; offv[4 * i + 3] = t.w;
        }
        const float4* a4 = reinterpret_cast<const float4*>(aw + (size_t)unit * 12);
#pragma unroll
        for (int i = 0; i < 3; i++) {
            float4 t = a4[i];
            lg[4 * i + 0] = t.x; lg[4 * i + 1] = t.y;
            lg[4 * i + 2] = t.z; lg[4 * i + 3] = t.w;
        }
    }

    // softmax over 12 logits
    float mx = -1e30f;
#pragma unroll
    for (int j = 0; j < 12; j++) mx = fmaxf(mx, lg[j]);
    float ssum = 0.f;
#pragma unroll
    for (int j = 0; j < 12; j++) { lg[j] = __expf(lg[j] - mx); ssum += lg[j]; }
    const float sinv = 1.f / ssum;

    float acc[8];
#pragma unroll
    for (int d = 0; d < 8; d++) acc[d] = 0.f;

    // element offset of this lane's 8-dim slice within a token row (fp8: 1B/elem)
    const uint32_t hoff = (uint32_t)(h * HDIM + ln8 * 8);

#pragma unroll
    for (int l = 0; l < NLVL; l++) {
        const int w_ = lvl_w[l], h_ = lvl_h[l];
        const float fw = (float)w_, fh = (float)h_;
        const float invw = 1.f / fw, invh = 1.f / fh;
        const uint32_t base_tok = (uint32_t)(b * LIN + lvl_s[l]);
#pragma unroll
        for (int p = 0; p < NPT; p++) {
            const float ox = offv[(l * NPT + p) * 2];
            const float oy = offv[(l * NPT + p) * 2 + 1];
            const float a  = lg[l * NPT + p] * sinv;
            const float x = (rx + ox * invw) * fw - 0.5f;
            const float y = (ry + oy * invh) * fh - 0.5f;
            const float x0f = floorf(x), y0f = floorf(y);
            const float wx = x - x0f, wy = y - y0f;
            const int x0 = (int)x0f, y0 = (int)y0f;
            const int x1 = x0 + 1, y1 = y0 + 1;

            const float vx0 = ((unsigned)x0 < (unsigned)w_) ? 1.f : 0.f;
            const float vx1 = ((unsigned)x1 < (unsigned)w_) ? 1.f : 0.f;
            const float vy0 = ((unsigned)y0 < (unsigned)h_) ? 1.f : 0.f;
            const float vy1 = ((unsigned)y1 < (unsigned)h_) ? 1.f : 0.f;
            const int x0c = min(max(x0, 0), w_ - 1);
            const int x1c = min(max(x1, 0), w_ - 1);
            const int y0c = min(max(y0, 0), h_ - 1);
            const int y1c = min(max(y1, 0), h_ - 1);

            const float w00 = (1.f - wx) * (1.f - wy) * a * vx0 * vy0;
            const float w01 = wx * (1.f - wy) * a * vx1 * vy0;
            const float w10 = (1.f - wx) * wy * a * vx0 * vy1;
            const float w11 = wx * wy * a * vx1 * vy1;

            const uint32_t e00 = (base_tok + (uint32_t)(y0c * w_ + x0c)) * 768u + hoff;
            const uint32_t e01 = (base_tok + (uint32_t)(y0c * w_ + x1c)) * 768u + hoff;
            const uint32_t e10 = (base_tok + (uint32_t)(y1c * w_ + x0c)) * 768u + hoff;
            const uint32_t e11 = (base_tok + (uint32_t)(y1c * w_ + x1c)) * 768u + hoff;

            const uint2 r00 = *reinterpret_cast<const uint2*>(val + e00);
            const uint2 r01 = *reinterpret_cast<const uint2*>(val + e01);
            const uint2 r10 = *reinterpret_cast<const uint2*>(val + e10);
            const uint2 r11 = *reinterpret_cast<const uint2*>(val + e11);

#pragma unroll
            for (int half = 0; half < 2; half++) {
                const uint32_t u00 = half ? r00.y : r00.x;
                const uint32_t u01 = half ? r01.y : r01.x;
                const uint32_t u10 = half ? r10.y : r10.x;
                const uint32_t u11 = half ? r11.y : r11.x;
                float4 f00 = unpack4_e4m3(u00);
                float4 f01 = unpack4_e4m3(u01);
                float4 f10 = unpack4_e4m3(u10);
                float4 f11 = unpack4_e4m3(u11);
                const int d = half * 4;
                acc[d + 0] += w00 * f00.x + w01 * f01.x + w10 * f10.x + w11 * f11.x;
                acc[d + 1] += w00 * f00.y + w01 * f01.y + w10 * f10.y + w11 * f11.y;
                acc[d + 2] += w00 * f00.z + w01 * f01.z + w10 * f10.z + w11 * f11.z;
                acc[d + 3] += w00 * f00.w + w01 * f01.w + w10 * f10.w + w11 * f11.w;
            }
        }
    }

    // store 8 bf16 dims (16B, aligned)
    const size_t so = (size_t)bq * DMODEL + h * HDIM + ln8 * 8;
    __nv_bfloat162 p0, p1, p2, p3;
    p0.x = __float2bfloat16(acc[0]); p0.y = __float2bfloat16(acc[1]);
    p1.x = __float2bfloat16(acc[2]); p1.y = __float2bfloat16(acc[3]);
    p2.x = __float2bfloat16(acc[4]); p2.y = __float2bfloat16(acc[5]);
    p3.x = __float2bfloat16(acc[6]); p3.y = __float2bfloat16(acc[7]);
    uint4 w;
    w.x = *reinterpret_cast<uint32_t*>(&p0);
    w.y = *reinterpret_cast<uint32_t*>(&p1);
    w.z = *reinterpret_cast<uint32_t*>(&p2);
    w.w = *reinterpret_cast<uint32_t*>(&p3);
    *reinterpret_cast<uint4*>(sam + so) = w;
}

// ---------------------------------------------------------------------------
// Launch (ordered so launch index 3 = value GEMM for ncu capture)
// ---------------------------------------------------------------------------
extern "C" void kernel_launch(void* const* d_in, const int* in_sizes, int n_in,
                              void* d_out, int out_size)
{
    const float* query  = (const float*)d_in[0];
    const float* feat   = (const float*)d_in[1];
    const float* ln_q_g = (const float*)d_in[2];
    const float* ln_q_b = (const float*)d_in[3];
    const float* ln_f_g = (const float*)d_in[4];
    const float* ln_f_b = (const float*)d_in[5];
    const float* W_off  = (const float*)d_in[6];
    const float* b_off  = (const float*)d_in[7];
    const float* W_attn = (const float*)d_in[8];
    const float* b_attn = (const float*)d_in[9];
    const float* W_val  = (const float*)d_in[10];
    const float* b_val  = (const float*)d_in[11];
    const float* W_out  = (const float*)d_in[12];
    const float* b_out  = (const float*)d_in[13];
    const float* gamma  = (const float*)d_in[14];
    float* out = (float*)d_out;

    __nv_bfloat16 *p_qln, *p_fln, *p_sam, *p_WvalT, *p_WoutT, *p_WcombT;
    uint8_t *p_val8;
    float *p_off, *p_aw;
    cudaGetSymbolAddress((void**)&p_qln,   g_qln);
    cudaGetSymbolAddress((void**)&p_fln,   g_fln);
    cudaGetSymbolAddress((void**)&p_val8,  g_val8);
    cudaGetSymbolAddress((void**)&p_sam,   g_sam);
    cudaGetSymbolAddress((void**)&p_WvalT, g_WvalT);
    cudaGetSymbolAddress((void**)&p_WoutT, g_WoutT);
    cudaGetSymbolAddress((void**)&p_WcombT,g_WcombT);
    cudaGetSymbolAddress((void**)&p_off,   g_off);
    cudaGetSymbolAddress((void**)&p_aw,    g_aw);

    cudaFuncSetAttribute(gemm_mma_kernel<0>, cudaFuncAttributeMaxDynamicSharedMemorySize, GEMM_SMEM);
    cudaFuncSetAttribute(gemm_mma_kernel<1>, cudaFuncAttributeMaxDynamicSharedMemorySize, GEMM_SMEM);
    cudaFuncSetAttribute(gemm_mma_kernel<2>, cudaFuncAttributeMaxDynamicSharedMemorySize, GEMM_SMEM);

    const int Mq = BATCH * LQ;    // 16384
    const int Mf = BATCH * LIN;   // 65856

    // 0,1: LayerNorms
    ln_kernel<<<(Mf + 7) / 8, 256>>>(feat, ln_f_g, ln_f_b, p_fln, Mf);
    ln_kernel<<<(Mq + 7) / 8, 256>>>(query, ln_q_g, ln_q_b, p_qln, Mq);

    // 2: W_val transpose
    wtransT_kernel<<<dim3(DMODEL / 32, DMODEL / 32), 256>>>(W_val, p_WvalT, DMODEL, DMODEL);

    // 3: value = ln(feat) @ W_val + b_val  (bf16 compute -> e4m3 storage)  [profiled]
    gemm_mma_kernel<0><<<dim3((Mf + BM - 1) / BM, DMODEL / BN), 256, GEMM_SMEM>>>(
        p_fln, p_WvalT, Mf, b_val, nullptr, p_val8, nullptr, nullptr, nullptr);

    // 4: comb weight transpose
    wtransC_kernel<<<dim3(DMODEL / 32, NCOMB_PAD / 32), 256>>>(W_off, W_attn, p_WcombT);

    // 5: fused offsets+attn logits (split epilogue)
    gemm_mma_kernel<1><<<dim3(Mq / BM, NCOMB_PAD / BN), 256, GEMM_SMEM>>>(
        p_qln, p_WcombT, Mq, b_off, b_attn, p_off, p_aw, nullptr, nullptr);

    // 6: W_out transpose
    wtransT_kernel<<<dim3(DMODEL / 32, DMODEL / 32), 256>>>(W_out, p_WoutT, DMODEL, DMODEL);

    // 7: deformable sampling with fused softmax -> g_sam (bf16)
    {
        const int units = Mq * NHEAD;           // 196608
        const int warps = units / 4;            // 49152
        sample_kernel<<<warps / 8, 256>>>(p_off, p_aw, p_val8, p_sam);
    }

    // 8: out = query + gamma * (g_sam @ W_out + b_out)
    gemm_mma_kernel<2><<<dim3(Mq / BM, DMODEL / BN), 256, GEMM_SMEM>>>(
        p_sam, p_WoutT, Mq, b_out, nullptr, out, nullptr, query, gamma);
}

// round 15
// speedup vs baseline: 1.4988x; 1.0360x over previous
#include <cuda_runtime.h>
#include <cuda_bf16.h>
#include <cstdint>

// ---------------------------------------------------------------------------
// Problem constants
// ---------------------------------------------------------------------------
#define BATCH 4
#define DMODEL 768
#define NHEAD 12
#define HDIM 64
#define NLVL 3
#define NPT 4
#define LQ 4096           // 64 x 64 query grid
#define LIN 16464         // 112*112 + 56*56 + 28*28
#define NOFF 288          // NH*NL*NP*2
#define NATT 144          // NH*NL*NP
#define NCOMB 432         // NOFF+NATT
#define NCOMB_PAD 512

// GEMM tiling: CTA 128x128, 4 warps (2x2), warp tile 64x64, BK=64, 2-stage
#define BM 128
#define BN 128
#define BK 64
#define ROWE 72            // bf16 elements per SMEM row (64 + 8 pad) = 144 B
#define KTILES (DMODEL / BK)   // 12
#define TILEB (BM * ROWE * 2)  // 18432 B per matrix-stage
#define GEMM_SMEM (4 * TILEB)  // 73728 B

// ---------------------------------------------------------------------------
// Scratch (device globals; no runtime allocation allowed)
// ---------------------------------------------------------------------------
__device__ __nv_bfloat16 g_qln[(size_t)BATCH * LQ * DMODEL];
__device__ __nv_bfloat16 g_fln[(size_t)BATCH * LIN * DMODEL];
__device__ uint8_t       g_val8[(size_t)BATCH * LIN * DMODEL];   // e4m3 storage
__device__ float         g_off[(size_t)BATCH * LQ * NOFF];
__device__ float         g_aw [(size_t)BATCH * LQ * NATT];
__device__ __nv_bfloat16 g_sam[(size_t)BATCH * LQ * DMODEL];
__device__ __nv_bfloat16 g_WvalT[DMODEL * DMODEL];        // [n][k]
__device__ __nv_bfloat16 g_WoutT[DMODEL * DMODEL];        // [n][k]
__device__ __nv_bfloat16 g_WcombT[NCOMB_PAD * DMODEL];    // [n][k], rows >=432 zero

// ---------------------------------------------------------------------------
// helpers
// ---------------------------------------------------------------------------
__device__ __forceinline__ uint32_t smem_u32(const void* p) {
    uint32_t a;
    asm("{ .reg .u64 t; cvta.to.shared.u64 t, %1; cvt.u32.u64 %0, t; }" : "=r"(a) : "l"(p));
    return a;
}

#define CP_ASYNC16(sp, gp) \
    asm volatile("cp.async.cg.shared.global [%0], [%1], 16;" :: "r"(sp), "l"(gp) : "memory")
#define CP_COMMIT() asm volatile("cp.async.commit_group;" ::: "memory")
#define CP_WAIT1()  asm volatile("cp.async.wait_group 1;" ::: "memory")

#define LDSM_X4(r, addr)                                                      \
    asm volatile("ldmatrix.sync.aligned.m8n8.x4.shared.b16 {%0,%1,%2,%3}, [%4];" \
        : "=r"((r)[0]), "=r"((r)[1]), "=r"((r)[2]), "=r"((r)[3]) : "r"(addr))
#define LDSM_X2(r, addr)                                                      \
    asm volatile("ldmatrix.sync.aligned.m8n8.x2.shared.b16 {%0,%1}, [%2];"    \
        : "=r"((r)[0]), "=r"((r)[1]) : "r"(addr))

#define MMA_16816(c, a, b)                                                    \
    asm volatile("mma.sync.aligned.m16n8k16.row.col.f32.bf16.bf16.f32 "       \
        "{%0,%1,%2,%3}, {%4,%5,%6,%7}, {%8,%9}, {%0,%1,%2,%3};"               \
        : "+f"((c)[0]), "+f"((c)[1]), "+f"((c)[2]), "+f"((c)[3])              \
        : "r"((a)[0]), "r"((a)[1]), "r"((a)[2]), "r"((a)[3]),                 \
          "r"((b)[0]), "r"((b)[1]))

// pack (lo, hi) floats -> e4m3x2 (lo in low byte)
__device__ __forceinline__ uint16_t pack_e4m3x2(float lo, float hi) {
    uint16_t r;
    asm("cvt.rn.satfinite.e4m3x2.f32 %0, %1, %2;" : "=h"(r) : "f"(hi), "f"(lo));
    return r;
}
// e4m3x2 -> float2 (exact via f16x2)
__device__ __forceinline__ float2 unpack_e4m3x2(uint16_t v) {
    uint32_t h2;
    asm("cvt.rn.f16x2.e4m3x2 %0, %1;" : "=r"(h2) : "h"(v));
    __half2 hh = *reinterpret_cast<__half2*>(&h2);
    return __half22float2(hh);
}
// 4 e4m3 bytes -> float4
__device__ __forceinline__ float4 unpack4_e4m3(uint32_t v) {
    float2 lo = unpack_e4m3x2((uint16_t)(v & 0xFFFFu));
    float2 hi = unpack_e4m3x2((uint16_t)(v >> 16));
    return make_float4(lo.x, lo.y, hi.x, hi.y);
}

// ---------------------------------------------------------------------------
// Tiled transpose fp32 [K,N] -> bf16 [N,K]  (32x32 smem tiles, coalesced)
// ---------------------------------------------------------------------------
__global__ void __launch_bounds__(256) wtransT_kernel(
    const float* __restrict__ W, __nv_bfloat16* __restrict__ Wt, int K, int N)
{
    __shared__ float t[32][33];
    const int kb = blockIdx.x * 32, nb = blockIdx.y * 32;
    const int tx = threadIdx.x & 31, ty = threadIdx.x >> 5;   // 32 x 8
#pragma unroll
    for (int i = 0; i < 32; i += 8) {
        int k = kb + ty + i, n = nb + tx;
        float v = (k < K && n < N) ? W[(size_t)k * N + n] : 0.f;
        t[ty + i][tx] = v;
    }
    __syncthreads();
#pragma unroll
    for (int i = 0; i < 32; i += 8) {
        int n = nb + ty + i, k = kb + tx;
        if (n < N && k < K)
            Wt[(size_t)n * K + k] = __float2bfloat16(t[tx][ty + i]);
    }
}

// combined off+attn transpose into padded [NCOMB_PAD, K]; rows >= NCOMB get 0
__global__ void __launch_bounds__(256) wtransC_kernel(
    const float* __restrict__ Woff, const float* __restrict__ Wattn,
    __nv_bfloat16* __restrict__ Wt)
{
    __shared__ float t[32][33];
    const int kb = blockIdx.x * 32, nb = blockIdx.y * 32;
    const int tx = threadIdx.x & 31, ty = threadIdx.x >> 5;
#pragma unroll
    for (int i = 0; i < 32; i += 8) {
        int k = kb + ty + i, n = nb + tx;
        float v = 0.f;
        if (k < DMODEL) {
            if (n < NOFF) v = Woff[(size_t)k * NOFF + n];
            else if (n < NCOMB) v = Wattn[(size_t)k * NATT + (n - NOFF)];
        }
        t[ty + i][tx] = v;
    }
    __syncthreads();
#pragma unroll
    for (int i = 0; i < 32; i += 8) {
        int n = nb + ty + i, k = kb + tx;
        if (n < NCOMB_PAD && k < DMODEL)
            Wt[(size_t)n * DMODEL + k] = __float2bfloat16(t[tx][ty + i]);
    }
}

// ---------------------------------------------------------------------------
// LayerNorm: one warp per row (768), float4 loads, shuffle-only reduction
// ---------------------------------------------------------------------------
__global__ void __launch_bounds__(256) ln_kernel(
    const float* __restrict__ x, const float* __restrict__ g,
    const float* __restrict__ b, __nv_bfloat16* __restrict__ out, int nrows)
{
    const int row = blockIdx.x * 8 + (threadIdx.x >> 5);
    const int lane = threadIdx.x & 31;
    if (row >= nrows) return;
    const float4* xr = reinterpret_cast<const float4*>(x + (size_t)row * DMODEL);
    float4 v[6];
    float s = 0.f, s2 = 0.f;
#pragma unroll
    for (int i = 0; i < 6; i++) {
        v[i] = xr[i * 32 + lane];
        s  += v[i].x + v[i].y + v[i].z + v[i].w;
        s2 += v[i].x * v[i].x + v[i].y * v[i].y + v[i].z * v[i].z + v[i].w * v[i].w;
    }
#pragma unroll
    for (int o = 16; o > 0; o >>= 1) {
        s  += __shfl_xor_sync(0xFFFFFFFFu, s,  o);
        s2 += __shfl_xor_sync(0xFFFFFFFFu, s2, o);
    }
    const float mean = s * (1.f / DMODEL);
    const float var  = s2 * (1.f / DMODEL) - mean * mean;
    const float rstd = rsqrtf(var + 1e-6f);
    const float4* gp = reinterpret_cast<const float4*>(g);
    const float4* bp = reinterpret_cast<const float4*>(b);
    uint2* o = reinterpret_cast<uint2*>(out + (size_t)row * DMODEL);
#pragma unroll
    for (int i = 0; i < 6; i++) {
        float4 gv = gp[i * 32 + lane];
        float4 bv = bp[i * 32 + lane];
        __nv_bfloat162 p0, p1;
        p0.x = __float2bfloat16((v[i].x - mean) * rstd * gv.x + bv.x);
        p0.y = __float2bfloat16((v[i].y - mean) * rstd * gv.y + bv.y);
        p1.x = __float2bfloat16((v[i].z - mean) * rstd * gv.z + bv.z);
        p1.y = __float2bfloat16((v[i].w - mean) * rstd * gv.w + bv.w);
        uint2 w;
        w.x = *reinterpret_cast<uint32_t*>(&p0);
        w.y = *reinterpret_cast<uint32_t*>(&p1);
        o[i * 32 + lane] = w;
    }
}

// ---------------------------------------------------------------------------
// mma.sync bf16 GEMM: CTA 128x128, 4 warps (2x2), warp tile 64x64,
// k-chunks of 64, cp.async double buffer, ldmatrix fragments, fp32 accum.
// 128 B smem traffic per MMA (vs 192 before) -> tensor-bound.
// EPI 0: e4m3 C (value)   EPI 1: split off(288)/attn(144) float
// EPI 2: float out = resid + gamma*(acc+bias)
// ---------------------------------------------------------------------------
template <int EPI>
__global__ void __launch_bounds__(128) gemm_mma_kernel(
    const __nv_bfloat16* __restrict__ A, const __nv_bfloat16* __restrict__ Bt,
    int M, const float* __restrict__ bias0, const float* __restrict__ bias1,
    void* __restrict__ out0, void* __restrict__ out1,
    const float* __restrict__ resid, const float* __restrict__ gamma)
{
    extern __shared__ char smem[];
    const uint32_t sbase = smem_u32(smem);

    const int tid  = threadIdx.x;
    const int wid  = tid >> 5;
    const int lane = tid & 31;
    const int wm   = wid >> 1;        // 0..1  (64-row block)
    const int wn   = wid & 1;         // 0..1  (64-col block)
    const int m0   = blockIdx.x * BM;
    const int n0   = blockIdx.y * BN;

    // layout: [A0][B0][A1][B1], each TILEB bytes
    const uint32_t aOff[2] = {sbase, sbase + 2 * TILEB};
    const uint32_t bOff[2] = {sbase + TILEB, sbase + 3 * TILEB};

    float acc[4][8][4];
#pragma unroll
    for (int mi = 0; mi < 4; mi++)
#pragma unroll
        for (int ni = 0; ni < 8; ni++)
#pragma unroll
            for (int r = 0; r < 4; r++) acc[mi][ni][r] = 0.f;

    // 1024 16B-chunks per matrix-tile, 8 per thread (128 threads)
    auto load_tile = [&](int kt, int s) {
        const int k0 = kt * BK;
#pragma unroll
        for (int t = 0; t < 8; t++) {
            int c = t * 128 + tid;
            int row = c >> 3, col = c & 7;
            int ar = m0 + row; if (ar >= M) ar = M - 1;
            CP_ASYNC16(aOff[s] + row * (ROWE * 2) + col * 16,
                       A + (size_t)ar * DMODEL + k0 + col * 8);
            CP_ASYNC16(bOff[s] + row * (ROWE * 2) + col * 16,
                       Bt + (size_t)(n0 + row) * DMODEL + k0 + col * 8);
        }
    };

    // ldmatrix lane addressing
    const int alr = lane & 15;            // A row within 16
    const int alc = lane >> 4;            // A col half (+8 elems)
    const int blr = lane & 7;             // B row within 8
    const int blc = (lane >> 3) & 1;      // B k half

    load_tile(0, 0);
    CP_COMMIT();

#pragma unroll 1
    for (int kt = 0; kt < KTILES; kt++) {
        const int s = kt & 1;
        if (kt + 1 < KTILES) load_tile(kt + 1, (kt + 1) & 1);
        CP_COMMIT();
        CP_WAIT1();
        __syncthreads();

        const uint32_t aBase = aOff[s] + (wm * 64 + alr) * (ROWE * 2) + alc * 16;
        const uint32_t bBase = bOff[s] + (wn * 64 + blr) * (ROWE * 2) + blc * 16;
#pragma unroll
        for (int ks = 0; ks < 4; ks++) {
            uint32_t af[4][4], bf[8][2];
#pragma unroll
            for (int mi = 0; mi < 4; mi++)
                LDSM_X4(af[mi], aBase + mi * 16 * (ROWE * 2) + ks * 32);
#pragma unroll
            for (int ni = 0; ni < 8; ni++)
                LDSM_X2(bf[ni], bBase + ni * 8 * (ROWE * 2) + ks * 32);
#pragma unroll
            for (int mi = 0; mi < 4; mi++)
#pragma unroll
                for (int ni = 0; ni < 8; ni++)
                    MMA_16816(acc[mi][ni], af[mi], bf[ni]);
        }
        __syncthreads();
    }

    // ---------------- epilogue ----------------
    const int groupID = lane >> 2, tig = lane & 3;
#pragma unroll
    for (int mi = 0; mi < 4; mi++) {
        const int r0 = m0 + wm * 64 + mi * 16 + groupID;
        const int r1 = r0 + 8;
#pragma unroll
        for (int ni = 0; ni < 8; ni++) {
            const int cb = n0 + wn * 64 + ni * 8 + tig * 2;
            const float* a4 = acc[mi][ni];
            if (EPI == 0) {
                uint8_t* o = (uint8_t*)out0;
                float b0v = bias0[cb], b1v = bias0[cb + 1];
                if (r0 < M)
                    *reinterpret_cast<uint16_t*>(o + (size_t)r0 * DMODEL + cb) =
                        pack_e4m3x2(a4[0] + b0v, a4[1] + b1v);
                if (r1 < M)
                    *reinterpret_cast<uint16_t*>(o + (size_t)r1 * DMODEL + cb) =
                        pack_e4m3x2(a4[2] + b0v, a4[3] + b1v);
            } else if (EPI == 1) {
                float* o0 = (float*)out0;
                float* o1 = (float*)out1;
#pragma unroll
                for (int e = 0; e < 2; e++) {
                    int n = cb + e;
                    float v0 = a4[e], v1 = a4[2 + e];
                    if (n < NOFF) {
                        o0[(size_t)r0 * NOFF + n] = v0 + bias0[n];
                        o0[(size_t)r1 * NOFF + n] = v1 + bias0[n];
                    } else if (n < NCOMB) {
                        o1[(size_t)r0 * NATT + (n - NOFF)] = v0 + bias1[n - NOFF];
                        o1[(size_t)r1 * NATT + (n - NOFF)] = v1 + bias1[n - NOFF];
                    }
                }
            } else {
                float* o = (float*)out0;
#pragma unroll
                for (int e = 0; e < 2; e++) {
                    int n = cb + e;
                    o[(size_t)r0 * DMODEL + n] = resid[(size_t)r0 * DMODEL + n] +
                                                 gamma[n] * (a4[e] + bias0[n]);
                    o[(size_t)r1 * DMODEL + n] = resid[(size_t)r1 * DMODEL + n] +
                                                 gamma[n] * (a4[2 + e] + bias0[n]);
                }
            }
        }
    }
}

// ---------------------------------------------------------------------------
// Deformable sampling + fused softmax.
// 4 units per warp: 8 lanes per (b,q,h), each lane owns 8 of 64 dims.
// Branch-free corners, 32-bit addressing, fp8 value gathers.
// ---------------------------------------------------------------------------
__global__ void __launch_bounds__(256) sample_kernel(
    const float* __restrict__ off, const float* __restrict__ aw,
    const uint8_t* __restrict__ val, __nv_bfloat16* __restrict__ sam)
{
    constexpr int lvl_h[3] = {112, 56, 28};
    constexpr int lvl_w[3] = {112, 56, 28};
    constexpr int lvl_s[3] = {0, 12544, 15680};

    const int warp = (blockIdx.x * blockDim.x + threadIdx.x) >> 5;
    const int lane = threadIdx.x & 31;
    const int grp  = lane >> 3;          // unit within warp (0..3)
    const int ln8  = lane & 7;           // lane within unit, 8 dims each
    const int unit = warp * 4 + grp;     // (b*LQ+q)*NHEAD + h
    if (unit >= BATCH * LQ * NHEAD) return;

    const int h  = unit % NHEAD;
    const int bq = unit / NHEAD;
    const int q  = bq & (LQ - 1);
    const int b  = bq >> 12;

    const float rx = ((q & 63) + 0.5f) * (1.f / 64.f);
    const float ry = ((q >> 6) + 0.5f) * (1.f / 64.f);

    // per-unit offsets + logits (broadcast within 8-lane group)
    float offv[24], lg[12];
    {
        const float4* o4 = reinterpret_cast<const float4*>(off + (size_t)unit * 24);
#pragma unroll
        for (int i = 0; i < 6; i++) {
            float4 t = o4[i];
            offv[4 * i + 0] = t.x; offv[4 * i + 1] = t.y;
            offv[4 * i + 2] = t.z; offv[4 * i + 3] = t.w;
        }
        const float4* a4 = reinterpret_cast<const float4*>(aw + (size_t)unit * 12);
#pragma unroll
        for (int i = 0; i < 3; i++) {
            float4 t = a4[i];
            lg[4 * i + 0] = t.x; lg[4 * i + 1] = t.y;
            lg[4 * i + 2] = t.z; lg[4 * i + 3] = t.w;
        }
    }

    // softmax over 12 logits
    float mx = -1e30f;
#pragma unroll
    for (int j = 0; j < 12; j++) mx = fmaxf(mx, lg[j]);
    float ssum = 0.f;
#pragma unroll
    for (int j = 0; j < 12; j++) { lg[j] = __expf(lg[j] - mx); ssum += lg[j]; }
    const float sinv = 1.f / ssum;

    float acc[8];
#pragma unroll
    for (int d = 0; d < 8; d++) acc[d] = 0.f;

    // element offset of this lane's 8-dim slice within a token row (fp8: 1B/elem)
    const uint32_t hoff = (uint32_t)(h * HDIM + ln8 * 8);

#pragma unroll
    for (int l = 0; l < NLVL; l++) {
        const int w_ = lvl_w[l], h_ = lvl_h[l];
        const float fw = (float)w_, fh = (float)h_;
        const float invw = 1.f / fw, invh = 1.f / fh;
        const uint32_t base_tok = (uint32_t)(b * LIN + lvl_s[l]);
#pragma unroll
        for (int p = 0; p < NPT; p++) {
            const float ox = offv[(l * NPT + p) * 2];
            const float oy = offv[(l * NPT + p) * 2 + 1];
            const float a  = lg[l * NPT + p] * sinv;
            const float x = (rx + ox * invw) * fw - 0.5f;
            const float y = (ry + oy * invh) * fh - 0.5f;
            const float x0f = floorf(x), y0f = floorf(y);
            const float wx = x - x0f, wy = y - y0f;
            const int x0 = (int)x0f, y0 = (int)y0f;
            const int x1 = x0 + 1, y1 = y0 + 1;

            const float vx0 = ((unsigned)x0 < (unsigned)w_) ? 1.f : 0.f;
            const float vx1 = ((unsigned)x1 < (unsigned)w_) ? 1.f : 0.f;
            const float vy0 = ((unsigned)y0 < (unsigned)h_) ? 1.f : 0.f;
            const float vy1 = ((unsigned)y1 < (unsigned)h_) ? 1.f : 0.f;
            const int x0c = min(max(x0, 0), w_ - 1);
            const int x1c = min(max(x1, 0), w_ - 1);
            const int y0c = min(max(y0, 0), h_ - 1);
            const int y1c = min(max(y1, 0), h_ - 1);

            const float w00 = (1.f - wx) * (1.f - wy) * a * vx0 * vy0;
            const float w01 = wx * (1.f - wy) * a * vx1 * vy0;
            const float w10 = (1.f - wx) * wy * a * vx0 * vy1;
            const float w11 = wx * wy * a * vx1 * vy1;

            const uint32_t e00 = (base_tok + (uint32_t)(y0c * w_ + x0c)) * 768u + hoff;
            const uint32_t e01 = (base_tok + (uint32_t)(y0c * w_ + x1c)) * 768u + hoff;
            const uint32_t e10 = (base_tok + (uint32_t)(y1c * w_ + x0c)) * 768u + hoff;
            const uint32_t e11 = (base_tok + (uint32_t)(y1c * w_ + x1c)) * 768u + hoff;

            const uint2 r00 = *reinterpret_cast<const uint2*>(val + e00);
            const uint2 r01 = *reinterpret_cast<const uint2*>(val + e01);
            const uint2 r10 = *reinterpret_cast<const uint2*>(val + e10);
            const uint2 r11 = *reinterpret_cast<const uint2*>(val + e11);

#pragma unroll
            for (int half = 0; half < 2; half++) {
                const uint32_t u00 = half ? r00.y : r00.x;
                const uint32_t u01 = half ? r01.y : r01.x;
                const uint32_t u10 = half ? r10.y : r10.x;
                const uint32_t u11 = half ? r11.y : r11.x;
                float4 f00 = unpack4_e4m3(u00);
                float4 f01 = unpack4_e4m3(u01);
                float4 f10 = unpack4_e4m3(u10);
                float4 f11 = unpack4_e4m3(u11);
                const int d = half * 4;
                acc[d + 0] += w00 * f00.x + w01 * f01.x + w10 * f10.x + w11 * f11.x;
                acc[d + 1] += w00 * f00.y + w01 * f01.y + w10 * f10.y + w11 * f11.y;
                acc[d + 2] += w00 * f00.z + w01 * f01.z + w10 * f10.z + w11 * f11.z;
                acc[d + 3] += w00 * f00.w + w01 * f01.w + w10 * f10.w + w11 * f11.w;
            }
        }
    }

    // store 8 bf16 dims (16B, aligned)
    const size_t so = (size_t)bq * DMODEL + h * HDIM + ln8 * 8;
    __nv_bfloat162 p0, p1, p2, p3;
    p0.x = __float2bfloat16(acc[0]); p0.y = __float2bfloat16(acc[1]);
    p1.x = __float2bfloat16(acc[2]); p1.y = __float2bfloat16(acc[3]);
    p2.x = __float2bfloat16(acc[4]); p2.y = __float2bfloat16(acc[5]);
    p3.x = __float2bfloat16(acc[6]); p3.y = __float2bfloat16(acc[7]);
    uint4 w;
    w.x = *reinterpret_cast<uint32_t*>(&p0);
    w.y = *reinterpret_cast<uint32_t*>(&p1);
    w.z = *reinterpret_cast<uint32_t*>(&p2);
    w.w = *reinterpret_cast<uint32_t*>(&p3);
    *reinterpret_cast<uint4*>(sam + so) = w;
}

// ---------------------------------------------------------------------------
// Launch (ordered so launch index 3 = value GEMM for ncu capture)
// ---------------------------------------------------------------------------
extern "C" void kernel_launch(void* const* d_in, const int* in_sizes, int n_in,
                              void* d_out, int out_size)
{
    const float* query  = (const float*)d_in[0];
    const float* feat   = (const float*)d_in[1];
    const float* ln_q_g = (const float*)d_in[2];
    const float* ln_q_b = (const float*)d_in[3];
    const float* ln_f_g = (const float*)d_in[4];
    const float* ln_f_b = (const float*)d_in[5];
    const float* W_off  = (const float*)d_in[6];
    const float* b_off  = (const float*)d_in[7];
    const float* W_attn = (const float*)d_in[8];
    const float* b_attn = (const float*)d_in[9];
    const float* W_val  = (const float*)d_in[10];
    const float* b_val  = (const float*)d_in[11];
    const float* W_out  = (const float*)d_in[12];
    const float* b_out  = (const float*)d_in[13];
    const float* gamma  = (const float*)d_in[14];
    float* out = (float*)d_out;

    __nv_bfloat16 *p_qln, *p_fln, *p_sam, *p_WvalT, *p_WoutT, *p_WcombT;
    uint8_t *p_val8;
    float *p_off, *p_aw;
    cudaGetSymbolAddress((void**)&p_qln,   g_qln);
    cudaGetSymbolAddress((void**)&p_fln,   g_fln);
    cudaGetSymbolAddress((void**)&p_val8,  g_val8);
    cudaGetSymbolAddress((void**)&p_sam,   g_sam);
    cudaGetSymbolAddress((void**)&p_WvalT, g_WvalT);
    cudaGetSymbolAddress((void**)&p_WoutT, g_WoutT);
    cudaGetSymbolAddress((void**)&p_WcombT,g_WcombT);
    cudaGetSymbolAddress((void**)&p_off,   g_off);
    cudaGetSymbolAddress((void**)&p_aw,    g_aw);

    cudaFuncSetAttribute(gemm_mma_kernel<0>, cudaFuncAttributeMaxDynamicSharedMemorySize, GEMM_SMEM);
    cudaFuncSetAttribute(gemm_mma_kernel<1>, cudaFuncAttributeMaxDynamicSharedMemorySize, GEMM_SMEM);
    cudaFuncSetAttribute(gemm_mma_kernel<2>, cudaFuncAttributeMaxDynamicSharedMemorySize, GEMM_SMEM);

    const int Mq = BATCH * LQ;    // 16384
    const int Mf = BATCH * LIN;   // 65856

    // 0,1: LayerNorms
    ln_kernel<<<(Mf + 7) / 8, 256>>>(feat, ln_f_g, ln_f_b, p_fln, Mf);
    ln_kernel<<<(Mq + 7) / 8, 256>>>(query, ln_q_g, ln_q_b, p_qln, Mq);

    // 2: W_val transpose
    wtransT_kernel<<<dim3(DMODEL / 32, DMODEL / 32), 256>>>(W_val, p_WvalT, DMODEL, DMODEL);

    // 3: value = ln(feat) @ W_val + b_val  (bf16 compute -> e4m3 storage)  [profiled]
    gemm_mma_kernel<0><<<dim3((Mf + BM - 1) / BM, DMODEL / BN), 128, GEMM_SMEM>>>(
        p_fln, p_WvalT, Mf, b_val, nullptr, p_val8, nullptr, nullptr, nullptr);

    // 4: comb weight transpose
    wtransC_kernel<<<dim3(DMODEL / 32, NCOMB_PAD / 32), 256>>>(W_off, W_attn, p_WcombT);

    // 5: fused offsets+attn logits (split epilogue)
    gemm_mma_kernel<1><<<dim3(Mq / BM, NCOMB_PAD / BN), 128, GEMM_SMEM>>>(
        p_qln, p_WcombT, Mq, b_off, b_attn, p_off, p_aw, nullptr, nullptr);

    // 6: W_out transpose
    wtransT_kernel<<<dim3(DMODEL / 32, DMODEL / 32), 256>>>(W_out, p_WoutT, DMODEL, DMODEL);

    // 7: deformable sampling with fused softmax -> g_sam (bf16)
    {
        const int units = Mq * NHEAD;           // 196608
        const int warps = units / 4;            // 49152
        sample_kernel<<<warps / 8, 256>>>(p_off, p_aw, p_val8, p_sam);
    }

    // 8: out = query + gamma * (g_sam @ W_out + b_out)
    gemm_mma_kernel<2><<<dim3(Mq / BM, DMODEL / BN), 128, GEMM_SMEM>>>(
        p_sam, p_WoutT, Mq, b_out, nullptr, out, nullptr, query, gamma);
}